// round 1
// baseline (speedup 1.0000x reference)
#include <cuda_runtime.h>
#include <cstdint>
#include <cstddef>

// Problem dims
#define BB 256
#define TT 1024
#define II 128
#define CC 256
#define GG 512   // 2C
#define OO 10

// Scratch (static device globals -- allocation-free kernel_launch)
__device__ float g_xz[(size_t)TT * BB * GG];   // [t][b][g]  (512 MB)
__device__ float g_h[BB * CC];                 // final hidden state

__device__ __forceinline__ float fast_sigmoid(float x) {
    // accurate fast path: MUFU.EX2-based exp + MUFU.RCP division (~1e-7 rel err)
    return __fdividef(1.0f, 1.0f + __expf(-x));
}

// ============================================================================
// Phase 1: xz[t][b][:] = x[b][t][:] @ kernel + recurrent_bias
// M = B*T = 262144 (m = b*T + t), N = 512, K = 128. FP32 SIMT tiled GEMM.
// ============================================================================
__global__ void __launch_bounds__(256) xz_gemm_kernel(const float* __restrict__ x,
                                                      const float* __restrict__ wk,
                                                      const float* __restrict__ bias) {
    __shared__ float As[64][17];   // [m][k], padded
    __shared__ float Bs[16][68];   // [k][n], padded

    const int tid = threadIdx.x;
    const int m0 = blockIdx.y * 64;
    const int n0 = blockIdx.x * 64;
    const int tr = tid >> 4;   // 0..15
    const int tc = tid & 15;   // 0..15

    float acc[4][4] = {};

    for (int k0 = 0; k0 < II; k0 += 16) {
        #pragma unroll
        for (int i = 0; i < 4; i++) {
            int idx = tid + i * 256;
            int r = idx >> 4, kk = idx & 15;
            As[r][kk] = x[(size_t)(m0 + r) * II + (k0 + kk)];
        }
        #pragma unroll
        for (int i = 0; i < 4; i++) {
            int idx = tid + i * 256;
            int kk = idx >> 6, c = idx & 63;
            Bs[kk][c] = wk[(size_t)(k0 + kk) * GG + (n0 + c)];
        }
        __syncthreads();
        #pragma unroll
        for (int kk = 0; kk < 16; kk++) {
            float a0 = As[tr * 4 + 0][kk];
            float a1 = As[tr * 4 + 1][kk];
            float a2 = As[tr * 4 + 2][kk];
            float a3 = As[tr * 4 + 3][kk];
            float4 bv = *(const float4*)&Bs[kk][tc * 4];
            acc[0][0] += a0 * bv.x; acc[0][1] += a0 * bv.y; acc[0][2] += a0 * bv.z; acc[0][3] += a0 * bv.w;
            acc[1][0] += a1 * bv.x; acc[1][1] += a1 * bv.y; acc[1][2] += a1 * bv.z; acc[1][3] += a1 * bv.w;
            acc[2][0] += a2 * bv.x; acc[2][1] += a2 * bv.y; acc[2][2] += a2 * bv.z; acc[2][3] += a2 * bv.w;
            acc[3][0] += a3 * bv.x; acc[3][1] += a3 * bv.y; acc[3][2] += a3 * bv.z; acc[3][3] += a3 * bv.w;
        }
        __syncthreads();
    }

    float4 bz = *(const float4*)&bias[n0 + tc * 4];
    #pragma unroll
    for (int i = 0; i < 4; i++) {
        int m = m0 + tr * 4 + i;
        int b = m >> 10;          // m / T
        int t = m & (TT - 1);     // m % T
        float4 v;
        v.x = acc[i][0] + bz.x;
        v.y = acc[i][1] + bz.y;
        v.z = acc[i][2] + bz.z;
        v.w = acc[i][3] + bz.w;
        *(float4*)&g_xz[((size_t)t * BB + b) * GG + n0 + tc * 4] = v;
    }
}

// ============================================================================
// Phase 2: the recurrence. Cluster of 4 CTAs N-splits the 512 z-columns
// (interleaved f/g pairs so each CTA owns complete cells). W chunk (256x128
// fp32 = 128KB) resident in SMEM. h exchanged each step via st.shared::cluster
// into a double-buffered h tile, one barrier.cluster per step.
//
// grid = 128 CTAs = 32 batch tiles (8 rows each) x 4-CTA clusters.
// Thread map (256 thr): warp w (0..7), lane: row = lane>>2 (0..7), cg = lane&3.
// Thread owns row `row`, local cells cl0 = 8w + 2cg and cl0+1
// -> 4 Wt columns [16w+4cg, +4): (f_cl0, g_cl0, f_cl1, g_cl1).
// ============================================================================
#define NN    4      // cluster size (N-split)
#define MROWS 8      // batch rows per CTA
#define NCOLS 128    // z cols per CTA (64 cells x {f,g})
#define KH    256    // h length (= C)
#define WSTR  260    // padded strides (bank-conflict engineered, 16B-aligned rows)
#define HSTR  260

extern __shared__ float smem2[];

__global__ void __launch_bounds__(256) __cluster_dims__(NN, 1, 1)
janet_scan_kernel(const float* __restrict__ rk /* [C][2C] */) {
    float* Wt = smem2;                        // [NCOLS][WSTR]  col-major-of-W chunk: Wt[col][k]
    float* hb = smem2 + NCOLS * WSTR;         // [2][MROWS][HSTR] double-buffered h

    const int tid  = threadIdx.x;
    const int w    = tid >> 5;
    const int lane = tid & 31;
    const int row  = lane >> 2;
    const int cg   = lane & 3;

    const unsigned rank = blockIdx.x & (NN - 1);
    const unsigned tile = blockIdx.x >> 2;
    const int b   = (int)tile * MROWS + row;
    const int cl0 = 8 * w + 2 * cg;           // even, local cell index
    const int cb  = 2 * cl0;                  // Wt column base (16w + 4cg)

    // ---- load W chunk: Wt[2m][k] = rk[k][64*rank+m], Wt[2m+1][k] = rk[k][256+64*rank+m]
    for (int idx = tid; idx < NCOLS * KH; idx += 256) {
        int col = idx >> 8;       // /KH
        int k   = idx & (KH - 1);
        int m   = col >> 1;
        int gcol = (col & 1) ? (CC + 64 * (int)rank + m) : (64 * (int)rank + m);
        Wt[col * WSTR + k] = rk[(size_t)k * GG + gcol];
    }
    // ---- zero both h buffers
    for (int idx = tid; idx < 2 * MROWS * HSTR; idx += 256) hb[idx] = 0.0f;

    // ---- precompute peer DSMEM base addresses for hb
    uint32_t hb_addr = (uint32_t)__cvta_generic_to_shared(hb);
    uint32_t peer_hb[NN];
    #pragma unroll
    for (int r = 0; r < NN; r++) {
        asm volatile("mapa.shared::cluster.u32 %0, %1, %2;"
                     : "=r"(peer_hb[r]) : "r"(hb_addr), "r"(r));
    }

    // init done everywhere before any remote write can land
    asm volatile("barrier.cluster.arrive.aligned;" ::: "memory");
    asm volatile("barrier.cluster.wait.aligned;"   ::: "memory");

    const float* wc0 = &Wt[(cb + 0) * WSTR];
    const float* wc1 = &Wt[(cb + 1) * WSTR];
    const float* wc2 = &Wt[(cb + 2) * WSTR];
    const float* wc3 = &Wt[(cb + 3) * WSTR];

    float c0 = 0.0f, c1 = 0.0f;

    // xz addresses for this thread's cells
    size_t xz_idx = ((size_t)0 * BB + b) * GG + 64 * rank + cl0;
    float2 pf = *(const float2*)&g_xz[xz_idx];          // (xz_f[cl0], xz_f[cl0+1])
    float2 pg = *(const float2*)&g_xz[xz_idx + CC];     // (xz_g[cl0], xz_g[cl0+1])

    const uint32_t hcell_off = (64 * rank + cl0) * 4;   // byte offset of our cells in an h row

    for (int t = 0; t < TT; t++) {
        const int cur = t & 1;
        const float* hrow = &hb[(cur * MROWS + row) * HSTR];

        float a0 = 0.f, a1 = 0.f, a2 = 0.f, a3 = 0.f;
        #pragma unroll 4
        for (int k = 0; k < KH; k += 4) {
            float4 h4 = *(const float4*)&hrow[k];
            float4 w0 = *(const float4*)&wc0[k];
            float4 w1 = *(const float4*)&wc1[k];
            float4 w2 = *(const float4*)&wc2[k];
            float4 w3 = *(const float4*)&wc3[k];
            a0 += h4.x * w0.x + h4.y * w0.y + h4.z * w0.z + h4.w * w0.w;
            a1 += h4.x * w1.x + h4.y * w1.y + h4.z * w1.z + h4.w * w1.w;
            a2 += h4.x * w2.x + h4.y * w2.y + h4.z * w2.z + h4.w * w2.w;
            a3 += h4.x * w3.x + h4.y * w3.y + h4.z * w3.z + h4.w * w3.w;
        }

        float zf0 = a0 + pf.x;
        float zg0 = a1 + pg.x;
        float zf1 = a2 + pf.y;
        float zg1 = a3 + pg.y;

        // prefetch next step's xz (clamped; value unused at t==TT-1)
        size_t nidx = xz_idx + ((t + 1 < TT) ? (size_t)BB * GG : 0);
        pf = *(const float2*)&g_xz[nidx];
        pg = *(const float2*)&g_xz[nidx + CC];
        xz_idx = nidx;

        float f0 = fast_sigmoid(zf0);
        float f1 = fast_sigmoid(zf1);
        float g0 = 2.0f * fast_sigmoid(2.0f * zg0) - 1.0f;   // tanh(zg0)
        float g1 = 2.0f * fast_sigmoid(2.0f * zg1) - 1.0f;   // tanh(zg1)
        c0 = f0 * c0 + (1.0f - f0) * g0;
        c1 = f1 * c1 + (1.0f - f1) * g1;

        // broadcast new h cells into every cluster CTA's next h buffer
        const int nxt = cur ^ 1;
        uint32_t off = (uint32_t)((nxt * MROWS + row) * HSTR) * 4 + hcell_off;  // 8B aligned (cl0 even)
        uint64_t pv = ((uint64_t)__float_as_uint(c1) << 32) | (uint64_t)__float_as_uint(c0);
        #pragma unroll
        for (int r = 0; r < NN; r++) {
            asm volatile("st.shared::cluster.b64 [%0], %1;"
                         :: "r"(peer_hb[r] + off), "l"(pv) : "memory");
        }

        asm volatile("barrier.cluster.arrive.aligned;" ::: "memory");
        asm volatile("barrier.cluster.wait.aligned;"   ::: "memory");
    }

    // final h for this thread's cells
    g_h[b * CC + 64 * rank + cl0]     = c0;
    g_h[b * CC + 64 * rank + cl0 + 1] = c1;
}

// ============================================================================
// Phase 3: out = h_final @ dense_w + dense_b   (256x256 @ 256x10)
// ============================================================================
__global__ void __launch_bounds__(32) dense_kernel(const float* __restrict__ dw,
                                                   const float* __restrict__ db,
                                                   float* __restrict__ out) {
    int b = blockIdx.x;
    int o = threadIdx.x;
    if (o < OO) {
        float acc = 0.0f;
        #pragma unroll 8
        for (int c = 0; c < CC; c++) {
            acc += g_h[b * CC + c] * dw[c * OO + o];
        }
        out[b * OO + o] = acc + db[o];
    }
}

// ============================================================================
extern "C" void kernel_launch(void* const* d_in, const int* in_sizes, int n_in,
                              void* d_out, int out_size) {
    const float* x  = (const float*)d_in[0];
    const float* wk = (const float*)d_in[1];
    const float* rk = (const float*)d_in[2];
    const float* rb = (const float*)d_in[3];
    const float* dw = (const float*)d_in[4];
    const float* db = (const float*)d_in[5];
    float* out = (float*)d_out;

    // Phase 1: input projection GEMM
    dim3 g1(GG / 64, (BB * TT) / 64);
    xz_gemm_kernel<<<g1, 256>>>(x, wk, rb);

    // Phase 2: recurrence (dynamic smem > 48KB -> opt-in; idempotent, capture-safe)
    const int smem_bytes = (NCOLS * WSTR + 2 * MROWS * HSTR) * (int)sizeof(float); // 149760
    cudaFuncSetAttribute(janet_scan_kernel, cudaFuncAttributeMaxDynamicSharedMemorySize, smem_bytes);
    janet_scan_kernel<<<32 * NN, 256, smem_bytes>>>(rk);

    // Phase 3: final dense
    dense_kernel<<<BB, 32>>>(dw, db, out);
}

// round 2
// speedup vs baseline: 2.7600x; 2.7600x over previous
#include <cuda_runtime.h>
#include <cstdint>
#include <cstddef>

// Problem dims
#define BB 256
#define TT 1024
#define II 128
#define CC 256
#define GG 512   // 2C
#define OO 10

// Scratch (static device globals -- allocation-free kernel_launch)
__device__ float g_xz[(size_t)TT * BB * GG];   // [t][b][g]  (512 MB)
__device__ float g_h[BB * CC];                 // final hidden state

__device__ __forceinline__ float fast_sigmoid(float x) {
    return __fdividef(1.0f, 1.0f + __expf(-x));
}

// ============================================================================
// Phase 1: xz[t][b][:] = x[b][t][:] @ kernel + recurrent_bias
// (measured at the fp32-SIMT roofline: fma pipe ~49% = rt2 ceiling; unchanged)
// ============================================================================
__global__ void __launch_bounds__(256) xz_gemm_kernel(const float* __restrict__ x,
                                                      const float* __restrict__ wk,
                                                      const float* __restrict__ bias) {
    __shared__ float As[64][17];   // [m][k], padded
    __shared__ float Bs[16][68];   // [k][n], padded

    const int tid = threadIdx.x;
    const int m0 = blockIdx.y * 64;
    const int n0 = blockIdx.x * 64;
    const int tr = tid >> 4;   // 0..15
    const int tc = tid & 15;   // 0..15

    float acc[4][4] = {};

    for (int k0 = 0; k0 < II; k0 += 16) {
        #pragma unroll
        for (int i = 0; i < 4; i++) {
            int idx = tid + i * 256;
            int r = idx >> 4, kk = idx & 15;
            As[r][kk] = x[(size_t)(m0 + r) * II + (k0 + kk)];
        }
        #pragma unroll
        for (int i = 0; i < 4; i++) {
            int idx = tid + i * 256;
            int kk = idx >> 6, c = idx & 63;
            Bs[kk][c] = wk[(size_t)(k0 + kk) * GG + (n0 + c)];
        }
        __syncthreads();
        #pragma unroll
        for (int kk = 0; kk < 16; kk++) {
            float a0 = As[tr * 4 + 0][kk];
            float a1 = As[tr * 4 + 1][kk];
            float a2 = As[tr * 4 + 2][kk];
            float a3 = As[tr * 4 + 3][kk];
            float4 bv = *(const float4*)&Bs[kk][tc * 4];
            acc[0][0] += a0 * bv.x; acc[0][1] += a0 * bv.y; acc[0][2] += a0 * bv.z; acc[0][3] += a0 * bv.w;
            acc[1][0] += a1 * bv.x; acc[1][1] += a1 * bv.y; acc[1][2] += a1 * bv.z; acc[1][3] += a1 * bv.w;
            acc[2][0] += a2 * bv.x; acc[2][1] += a2 * bv.y; acc[2][2] += a2 * bv.z; acc[2][3] += a2 * bv.w;
            acc[3][0] += a3 * bv.x; acc[3][1] += a3 * bv.y; acc[3][2] += a3 * bv.z; acc[3][3] += a3 * bv.w;
        }
        __syncthreads();
    }

    float4 bz = *(const float4*)&bias[n0 + tc * 4];
    #pragma unroll
    for (int i = 0; i < 4; i++) {
        int m = m0 + tr * 4 + i;
        int b = m >> 10;          // m / T
        int t = m & (TT - 1);     // m % T
        float4 v;
        v.x = acc[i][0] + bz.x;
        v.y = acc[i][1] + bz.y;
        v.z = acc[i][2] + bz.z;
        v.w = acc[i][3] + bz.w;
        *(float4*)&g_xz[((size_t)t * BB + b) * GG + n0 + tc * 4] = v;
    }
}

// ============================================================================
// Phase 2: recurrence, W register-resident.
//
// Cluster of 4 CTAs N-splits the 512 z-cols (each CTA: 64 cells x {f,g}).
// Per CTA: 256 threads = 64 cells x 4 k-groups (KLEN=64 each).
// Thread holds wf[64], wg[64] in REGISTERS (128 regs), accumulates partial z
// for all MROWS=8 batch rows, butterfly-reduces over k-groups (lane bits 3,4).
// h lives in a double-buffered smem tile with an 8-float gap every 64 k so the
// 4 k-group LDS.128 addresses land in bank groups {0,8,16,24}: conflict-free,
// broadcast within a k-group. Per-step smem cost 1024 cyc << 4096 cyc FFMA.
// New h cells broadcast to all 4 cluster CTAs via st.shared::cluster, one
// barrier.cluster per step.
// ============================================================================
#define NN    4      // cluster size (N-split)
#define MROWS 8      // batch rows per CTA
#define KH    256    // h length (= C)
#define KGN   4      // k-groups
#define KLEN  64     // k per group
#define HSTR  288    // padded h row stride (256 + 4 gaps of 8), %32 == 0

__global__ void __launch_bounds__(256) __cluster_dims__(NN, 1, 1)
janet_scan_kernel(const float* __restrict__ rk /* [C][2C] */) {
    __shared__ __align__(16) float hb[2 * MROWS * HSTR];   // 18KB

    const int tid  = threadIdx.x;
    const int w    = tid >> 5;
    const int lane = tid & 31;
    const int kg   = lane >> 3;          // 0..3  (lane bits 3,4)
    const int cl   = lane & 7;           // 0..7
    const int cell = 8 * w + cl;         // 0..63 local cell

    const unsigned rank = blockIdx.x & (NN - 1);
    const unsigned tile = blockIdx.x >> 2;
    const int gcell = 64 * (int)rank + cell;   // global cell 0..255

    // ---- W chunk into registers: wf[j]=rk[64*kg+j][gcell], wg[j]=rk[..][CC+gcell]
    float wf[KLEN], wg[KLEN];
    {
        const float* rkf = rk + (size_t)(KLEN * kg) * GG + gcell;
        #pragma unroll
        for (int j = 0; j < KLEN; j++) {
            wf[j] = __ldg(rkf + (size_t)j * GG);
            wg[j] = __ldg(rkf + (size_t)j * GG + CC);
        }
    }

    // ---- zero both h buffers
    for (int i = tid; i < 2 * MROWS * HSTR; i += 256) hb[i] = 0.0f;

    // ---- peer DSMEM base addresses
    uint32_t hb_addr = (uint32_t)__cvta_generic_to_shared(hb);
    uint32_t peer_hb[NN];
    #pragma unroll
    for (int r = 0; r < NN; r++) {
        asm volatile("mapa.shared::cluster.u32 %0, %1, %2;"
                     : "=r"(peer_hb[r]) : "r"(hb_addr), "r"(r));
    }

    asm volatile("barrier.cluster.arrive.aligned;" ::: "memory");
    asm volatile("barrier.cluster.wait.aligned;"   ::: "memory");

    float c[MROWS];
    #pragma unroll
    for (int r = 0; r < MROWS; r++) c[r] = 0.0f;

    // xz pointer for (t=0, b=tile*8, gcell); row r at +r*GG, step at +BB*GG
    const float* xzp = g_xz + (size_t)(tile * MROWS) * GG + gcell;
    // padded smem position of gcell within an h row: gcell + 8*(gcell>>6)
    const int wpos = 72 * (int)rank + cell;

    for (int t = 0; t < TT; t++) {
        const int cur = t & 1;

        // xz loads for this step (latency hidden under the k-loop)
        float pf[MROWS], pg[MROWS];
        #pragma unroll
        for (int r = 0; r < MROWS; r++) {
            const float* p = xzp + (size_t)r * GG;
            pf[r] = __ldcs(p);
            pg[r] = __ldcs(p + CC);
        }
        xzp += (size_t)BB * GG;

        const float* hk = hb + cur * MROWS * HSTR + 72 * kg;

        float af[MROWS], ag[MROWS];
        #pragma unroll
        for (int r = 0; r < MROWS; r++) { af[r] = 0.0f; ag[r] = 0.0f; }

        #pragma unroll
        for (int jj = 0; jj < KLEN; jj += 4) {
            #pragma unroll
            for (int r = 0; r < MROWS; r++) {
                float4 h4 = *(const float4*)(hk + r * HSTR + jj);
                af[r] = fmaf(h4.x, wf[jj + 0], af[r]);
                af[r] = fmaf(h4.y, wf[jj + 1], af[r]);
                af[r] = fmaf(h4.z, wf[jj + 2], af[r]);
                af[r] = fmaf(h4.w, wf[jj + 3], af[r]);
                ag[r] = fmaf(h4.x, wg[jj + 0], ag[r]);
                ag[r] = fmaf(h4.y, wg[jj + 1], ag[r]);
                ag[r] = fmaf(h4.z, wg[jj + 2], ag[r]);
                ag[r] = fmaf(h4.w, wg[jj + 3], ag[r]);
            }
        }

        // reduce partials across the 4 k-groups (lane bits 3 and 4)
        #pragma unroll
        for (int r = 0; r < MROWS; r++) {
            af[r] += __shfl_xor_sync(0xffffffffu, af[r], 8);
            af[r] += __shfl_xor_sync(0xffffffffu, af[r], 16);
            ag[r] += __shfl_xor_sync(0xffffffffu, ag[r], 8);
            ag[r] += __shfl_xor_sync(0xffffffffu, ag[r], 16);
        }

        // gate update (computed redundantly in all 4 kg lanes -> identical c)
        #pragma unroll
        for (int r = 0; r < MROWS; r++) {
            float f = fast_sigmoid(af[r] + pf[r]);
            float g = 2.0f * fast_sigmoid(2.0f * (ag[r] + pg[r])) - 1.0f;  // tanh
            c[r] = f * c[r] + (1.0f - f) * g;
        }

        // broadcast new h: lane with k-group kg writes rows {2kg, 2kg+1} to all peers
        const int nxt = cur ^ 1;
        #pragma unroll
        for (int rr = 0; rr < 2; rr++) {
            const int r = 2 * kg + rr;
            uint32_t off = (uint32_t)((nxt * MROWS + r) * HSTR + wpos) * 4u;
            uint32_t v = __float_as_uint(c[r]);
            #pragma unroll
            for (int p = 0; p < NN; p++) {
                asm volatile("st.shared::cluster.b32 [%0], %1;"
                             :: "r"(peer_hb[p] + off), "r"(v) : "memory");
            }
        }

        asm volatile("barrier.cluster.arrive.aligned;" ::: "memory");
        asm volatile("barrier.cluster.wait.aligned;"   ::: "memory");
    }

    // final h (kg lanes hold identical values; write once)
    if (kg == 0) {
        #pragma unroll
        for (int r = 0; r < MROWS; r++) {
            g_h[((int)tile * MROWS + r) * CC + gcell] = c[r];
        }
    }
}

// ============================================================================
// Phase 3: out = h_final @ dense_w + dense_b   (256x256 @ 256x10)
// ============================================================================
__global__ void __launch_bounds__(32) dense_kernel(const float* __restrict__ dw,
                                                   const float* __restrict__ db,
                                                   float* __restrict__ out) {
    int b = blockIdx.x;
    int o = threadIdx.x;
    if (o < OO) {
        float acc = 0.0f;
        #pragma unroll 8
        for (int c = 0; c < CC; c++) {
            acc += g_h[b * CC + c] * dw[c * OO + o];
        }
        out[b * OO + o] = acc + db[o];
    }
}

// ============================================================================
extern "C" void kernel_launch(void* const* d_in, const int* in_sizes, int n_in,
                              void* d_out, int out_size) {
    const float* x  = (const float*)d_in[0];
    const float* wk = (const float*)d_in[1];
    const float* rk = (const float*)d_in[2];
    const float* rb = (const float*)d_in[3];
    const float* dw = (const float*)d_in[4];
    const float* db = (const float*)d_in[5];
    float* out = (float*)d_out;

    // Phase 1: input projection GEMM
    dim3 g1(GG / 64, (BB * TT) / 64);
    xz_gemm_kernel<<<g1, 256>>>(x, wk, rb);

    // Phase 2: recurrence (static smem only, 18KB)
    janet_scan_kernel<<<32 * NN, 256>>>(rk);

    // Phase 3: final dense
    dense_kernel<<<BB, 32>>>(dw, db, out);
}

// round 3
// speedup vs baseline: 2.8811x; 1.0439x over previous
#include <cuda_runtime.h>
#include <cstdint>
#include <cstddef>

// Problem dims
#define BB 256
#define TT 1024
#define II 128
#define CC 256
#define GG 512   // 2C
#define OO 10

// Scratch (static device globals -- allocation-free kernel_launch)
__device__ float g_xz[(size_t)TT * BB * GG];   // [t][b][g]  (512 MB)
__device__ float g_h[BB * CC];                 // final hidden state

__device__ __forceinline__ float fast_sigmoid(float x) {
    return __fdividef(1.0f, 1.0f + __expf(-x));
}

// ---- packed fp32x2 helpers (FFMA2: 2 MACs per issue slot, exact IEEE fp32) ----
__device__ __forceinline__ unsigned long long pack2(float lo, float hi) {
    unsigned long long r;
    asm("mov.b64 %0, {%1, %2};" : "=l"(r) : "f"(lo), "f"(hi));
    return r;
}
__device__ __forceinline__ void unpack2(unsigned long long v, float& lo, float& hi) {
    asm("mov.b64 {%0, %1}, %2;" : "=f"(lo), "=f"(hi) : "l"(v));
}
__device__ __forceinline__ void ffma2(unsigned long long& d, unsigned long long a,
                                      unsigned long long b) {
    asm("fma.rn.f32x2 %0, %1, %2, %0;" : "+l"(d) : "l"(a), "l"(b));
}

// ============================================================================
// Phase 1: xz[t][b][:] = x[b][t][:] @ kernel + recurrent_bias
// M = B*T = 262144, N = 512, K = 128. FFMA2 version: 8 packed MACs per kk
// replace 16 FFMA; As stored k-major so the A fragment is one LDS.128.
// ============================================================================
__global__ void __launch_bounds__(256) xz_gemm_kernel(const float* __restrict__ x,
                                                      const float* __restrict__ wk,
                                                      const float* __restrict__ bias) {
    __shared__ __align__(16) float As[16][68];   // [k][m], padded
    __shared__ __align__(16) float Bs[16][68];   // [k][n], padded

    const int tid = threadIdx.x;
    const int m0 = blockIdx.y * 64;
    const int n0 = blockIdx.x * 64;
    const int tr = tid >> 4;   // 0..15 -> m sub-tile
    const int tc = tid & 15;   // 0..15 -> n sub-tile

    unsigned long long acc2[4][2];
    #pragma unroll
    for (int i = 0; i < 4; i++) { acc2[i][0] = 0ull; acc2[i][1] = 0ull; }

    for (int k0 = 0; k0 < II; k0 += 16) {
        #pragma unroll
        for (int i = 0; i < 4; i++) {
            int idx = tid + i * 256;
            int r = idx >> 4, kk = idx & 15;
            As[kk][r] = x[(size_t)(m0 + r) * II + (k0 + kk)];
        }
        #pragma unroll
        for (int i = 0; i < 4; i++) {
            int idx = tid + i * 256;
            int kk = idx >> 6, c = idx & 63;
            Bs[kk][c] = wk[(size_t)(k0 + kk) * GG + (n0 + c)];
        }
        __syncthreads();
        #pragma unroll
        for (int kk = 0; kk < 16; kk++) {
            float4 a4 = *(const float4*)&As[kk][tr * 4];
            ulonglong2 b2 = *(const ulonglong2*)&Bs[kk][tc * 4];
            unsigned long long aa0 = pack2(a4.x, a4.x);
            unsigned long long aa1 = pack2(a4.y, a4.y);
            unsigned long long aa2 = pack2(a4.z, a4.z);
            unsigned long long aa3 = pack2(a4.w, a4.w);
            ffma2(acc2[0][0], aa0, b2.x); ffma2(acc2[0][1], aa0, b2.y);
            ffma2(acc2[1][0], aa1, b2.x); ffma2(acc2[1][1], aa1, b2.y);
            ffma2(acc2[2][0], aa2, b2.x); ffma2(acc2[2][1], aa2, b2.y);
            ffma2(acc2[3][0], aa3, b2.x); ffma2(acc2[3][1], aa3, b2.y);
        }
        __syncthreads();
    }

    float4 bz = *(const float4*)&bias[n0 + tc * 4];
    #pragma unroll
    for (int i = 0; i < 4; i++) {
        int m = m0 + tr * 4 + i;
        int b = m >> 10;          // m / T
        int t = m & (TT - 1);     // m % T
        float4 v;
        unpack2(acc2[i][0], v.x, v.y);
        unpack2(acc2[i][1], v.z, v.w);
        v.x += bz.x; v.y += bz.y; v.z += bz.z; v.w += bz.w;
        *(float4*)&g_xz[((size_t)t * BB + b) * GG + n0 + tc * 4] = v;
    }
}

// ============================================================================
// Phase 2: recurrence, W register-resident, FFMA2 mainloop.
//
// Cluster of 4 CTAs N-splits the 512 z-cols (each CTA: 64 cells x {f,g}).
// Per CTA: 256 threads = 64 cells x 4 k-groups (KLEN=64 each).
// Thread holds wf2[32], wg2[32] (packed k-pairs, 128 regs), accumulates packed
// partial z for all MROWS=8 batch rows (512 FFMA2/step), butterfly-reduces
// over k-groups. Gates/MUFU/xz-loads only for the lane's 2 owned rows (2*kg).
// h in double-buffered smem with 8-float gaps per 64 k (bank groups
// {0,8,16,24}: conflict-free broadcast). h broadcast to 4 cluster CTAs via
// st.shared::cluster + one barrier.cluster per step.
// ============================================================================
#define NN    4      // cluster size (N-split)
#define MROWS 8      // batch rows per CTA
#define KH    256    // h length (= C)
#define KGN   4      // k-groups
#define KLEN  64     // k per group
#define HSTR  288    // padded h row stride (256 + 4 gaps of 8), %32 == 0

__global__ void __launch_bounds__(256) __cluster_dims__(NN, 1, 1)
janet_scan_kernel(const float* __restrict__ rk /* [C][2C] */) {
    __shared__ __align__(16) float hb[2 * MROWS * HSTR];   // 18KB

    const int tid  = threadIdx.x;
    const int w    = tid >> 5;
    const int lane = tid & 31;
    const int kg   = lane >> 3;          // 0..3  (lane bits 3,4)
    const int cl   = lane & 7;           // 0..7
    const int cell = 8 * w + cl;         // 0..63 local cell

    const unsigned rank = blockIdx.x & (NN - 1);
    const unsigned tile = blockIdx.x >> 2;
    const int gcell = 64 * (int)rank + cell;   // global cell 0..255

    // ---- W chunk into packed registers:
    // wf2[j] = (rk[64*kg+2j][gcell], rk[64*kg+2j+1][gcell]); wg2 at col CC+gcell
    unsigned long long wf2[KLEN / 2], wg2[KLEN / 2];
    {
        const float* rkf = rk + (size_t)(KLEN * kg) * GG + gcell;
        #pragma unroll
        for (int j = 0; j < KLEN / 2; j++) {
            float f0 = __ldg(rkf + (size_t)(2 * j) * GG);
            float f1 = __ldg(rkf + (size_t)(2 * j + 1) * GG);
            float g0 = __ldg(rkf + (size_t)(2 * j) * GG + CC);
            float g1 = __ldg(rkf + (size_t)(2 * j + 1) * GG + CC);
            wf2[j] = pack2(f0, f1);
            wg2[j] = pack2(g0, g1);
        }
    }

    // ---- zero both h buffers
    for (int i = tid; i < 2 * MROWS * HSTR; i += 256) hb[i] = 0.0f;

    // ---- peer DSMEM base addresses
    uint32_t hb_addr = (uint32_t)__cvta_generic_to_shared(hb);
    uint32_t peer_hb[NN];
    #pragma unroll
    for (int r = 0; r < NN; r++) {
        asm volatile("mapa.shared::cluster.u32 %0, %1, %2;"
                     : "=r"(peer_hb[r]) : "r"(hb_addr), "r"(r));
    }

    asm volatile("barrier.cluster.arrive.aligned;" ::: "memory");
    asm volatile("barrier.cluster.wait.aligned;"   ::: "memory");

    // this lane owns batch rows 2*kg and 2*kg+1
    float c0 = 0.0f, c1 = 0.0f;
    const int r0 = 2 * kg;

    // xz pointer for (t=0, b=tile*8 + r0, gcell); step at +BB*GG
    const float* xzp = g_xz + (size_t)(tile * MROWS + r0) * GG + gcell;
    // padded smem position of gcell within an h row
    const int wpos = 72 * (int)rank + cell;

    for (int t = 0; t < TT; t++) {
        const int cur = t & 1;

        // xz loads for owned rows (latency hidden under the FMA loop)
        float pf0 = __ldcs(xzp);
        float pg0 = __ldcs(xzp + CC);
        float pf1 = __ldcs(xzp + GG);
        float pg1 = __ldcs(xzp + GG + CC);
        xzp += (size_t)BB * GG;

        const float* hk = hb + cur * MROWS * HSTR + 72 * kg;

        unsigned long long af2[MROWS], ag2[MROWS];
        #pragma unroll
        for (int r = 0; r < MROWS; r++) { af2[r] = 0ull; ag2[r] = 0ull; }

        #pragma unroll
        for (int jj = 0; jj < KLEN / 4; jj++) {      // 16 iters, 4 k each
            #pragma unroll
            for (int r = 0; r < MROWS; r++) {
                ulonglong2 h2 = *(const ulonglong2*)(hk + r * HSTR + 4 * jj);
                ffma2(af2[r], h2.x, wf2[2 * jj]);
                ffma2(af2[r], h2.y, wf2[2 * jj + 1]);
                ffma2(ag2[r], h2.x, wg2[2 * jj]);
                ffma2(ag2[r], h2.y, wg2[2 * jj + 1]);
            }
        }

        // combine packed halves + butterfly-reduce across the 4 k-groups
        float af[MROWS], ag[MROWS];
        #pragma unroll
        for (int r = 0; r < MROWS; r++) {
            float lo, hi;
            unpack2(af2[r], lo, hi); af[r] = lo + hi;
            unpack2(ag2[r], lo, hi); ag[r] = lo + hi;
            af[r] += __shfl_xor_sync(0xffffffffu, af[r], 8);
            af[r] += __shfl_xor_sync(0xffffffffu, af[r], 16);
            ag[r] += __shfl_xor_sync(0xffffffffu, ag[r], 8);
            ag[r] += __shfl_xor_sync(0xffffffffu, ag[r], 16);
        }

        // gate update for the 2 owned rows only
        {
            float f = fast_sigmoid(af[r0] + pf0);
            float g = 2.0f * fast_sigmoid(2.0f * (ag[r0] + pg0)) - 1.0f;  // tanh
            c0 = f * c0 + (1.0f - f) * g;
        }
        {
            float f = fast_sigmoid(af[r0 + 1] + pf1);
            float g = 2.0f * fast_sigmoid(2.0f * (ag[r0 + 1] + pg1)) - 1.0f;
            c1 = f * c1 + (1.0f - f) * g;
        }

        // broadcast new h cells for owned rows to all peers
        const int nxt = cur ^ 1;
        uint32_t off0 = (uint32_t)((nxt * MROWS + r0) * HSTR + wpos) * 4u;
        uint32_t off1 = off0 + (uint32_t)HSTR * 4u;
        uint32_t v0 = __float_as_uint(c0);
        uint32_t v1 = __float_as_uint(c1);
        #pragma unroll
        for (int p = 0; p < NN; p++) {
            asm volatile("st.shared::cluster.b32 [%0], %1;"
                         :: "r"(peer_hb[p] + off0), "r"(v0) : "memory");
            asm volatile("st.shared::cluster.b32 [%0], %1;"
                         :: "r"(peer_hb[p] + off1), "r"(v1) : "memory");
        }

        asm volatile("barrier.cluster.arrive.aligned;" ::: "memory");
        asm volatile("barrier.cluster.wait.aligned;"   ::: "memory");
    }

    // final h for owned rows
    g_h[((int)tile * MROWS + r0) * CC + gcell]     = c0;
    g_h[((int)tile * MROWS + r0 + 1) * CC + gcell] = c1;
}

// ============================================================================
// Phase 3: out = h_final @ dense_w + dense_b   (256x256 @ 256x10)
// ============================================================================
__global__ void __launch_bounds__(32) dense_kernel(const float* __restrict__ dw,
                                                   const float* __restrict__ db,
                                                   float* __restrict__ out) {
    int b = blockIdx.x;
    int o = threadIdx.x;
    if (o < OO) {
        float acc = 0.0f;
        #pragma unroll 8
        for (int c = 0; c < CC; c++) {
            acc += g_h[b * CC + c] * dw[c * OO + o];
        }
        out[b * OO + o] = acc + db[o];
    }
}

// ============================================================================
extern "C" void kernel_launch(void* const* d_in, const int* in_sizes, int n_in,
                              void* d_out, int out_size) {
    const float* x  = (const float*)d_in[0];
    const float* wk = (const float*)d_in[1];
    const float* rk = (const float*)d_in[2];
    const float* rb = (const float*)d_in[3];
    const float* dw = (const float*)d_in[4];
    const float* db = (const float*)d_in[5];
    float* out = (float*)d_out;

    // Phase 1: input projection GEMM
    dim3 g1(GG / 64, (BB * TT) / 64);
    xz_gemm_kernel<<<g1, 256>>>(x, wk, rb);

    // Phase 2: recurrence (static smem only, 18KB)
    janet_scan_kernel<<<32 * NN, 256>>>(rk);

    // Phase 3: final dense
    dense_kernel<<<BB, 32>>>(dw, db, out);
}

// round 12
// speedup vs baseline: 3.8086x; 1.3219x over previous
#include <cuda_runtime.h>
#include <cuda_bf16.h>
#include <cstdint>
#include <cstddef>

// Problem dims
#define BB 256
#define TT 1024
#define II 128
#define CC 256
#define GG 512   // 2C
#define OO 10

// Scratch (static device globals -- allocation-free kernel_launch)
__device__ float g_xz[(size_t)TT * BB * GG];   // [t][b][g]  (512 MB)
__device__ float g_h[BB * CC];                 // final hidden state

__device__ __forceinline__ float fast_sigmoid(float x) {
    return __fdividef(1.0f, 1.0f + __expf(-x));
}

// ---- packed fp32x2 helpers (phase-1 GEMM; kept from R3) ----
__device__ __forceinline__ unsigned long long pack2(float lo, float hi) {
    unsigned long long r;
    asm("mov.b64 %0, {%1, %2};" : "=l"(r) : "f"(lo), "f"(hi));
    return r;
}
__device__ __forceinline__ void unpack2(unsigned long long v, float& lo, float& hi) {
    asm("mov.b64 {%0, %1}, %2;" : "=f"(lo), "=f"(hi) : "l"(v));
}
__device__ __forceinline__ void ffma2(unsigned long long& d, unsigned long long a,
                                      unsigned long long b) {
    asm("fma.rn.f32x2 %0, %1, %2, %0;" : "+l"(d) : "l"(a), "l"(b));
}

// ============================================================================
// Phase 1: xz GEMM (proven at the fp32 FFMA roofline, 897us; unchanged)
// ============================================================================
__global__ void __launch_bounds__(256) xz_gemm_kernel(const float* __restrict__ x,
                                                      const float* __restrict__ wk,
                                                      const float* __restrict__ bias) {
    __shared__ __align__(16) float As[16][68];   // [k][m], padded
    __shared__ __align__(16) float Bs[16][68];   // [k][n], padded

    const int tid = threadIdx.x;
    const int m0 = blockIdx.y * 64;
    const int n0 = blockIdx.x * 64;
    const int tr = tid >> 4;
    const int tc = tid & 15;

    unsigned long long acc2[4][2];
    #pragma unroll
    for (int i = 0; i < 4; i++) { acc2[i][0] = 0ull; acc2[i][1] = 0ull; }

    for (int k0 = 0; k0 < II; k0 += 16) {
        #pragma unroll
        for (int i = 0; i < 4; i++) {
            int idx = tid + i * 256;
            int r = idx >> 4, kk = idx & 15;
            As[kk][r] = x[(size_t)(m0 + r) * II + (k0 + kk)];
        }
        #pragma unroll
        for (int i = 0; i < 4; i++) {
            int idx = tid + i * 256;
            int kk = idx >> 6, c = idx & 63;
            Bs[kk][c] = wk[(size_t)(k0 + kk) * GG + (n0 + c)];
        }
        __syncthreads();
        #pragma unroll
        for (int kk = 0; kk < 16; kk++) {
            float4 a4 = *(const float4*)&As[kk][tr * 4];
            ulonglong2 b2 = *(const ulonglong2*)&Bs[kk][tc * 4];
            unsigned long long aa0 = pack2(a4.x, a4.x);
            unsigned long long aa1 = pack2(a4.y, a4.y);
            unsigned long long aa2 = pack2(a4.z, a4.z);
            unsigned long long aa3 = pack2(a4.w, a4.w);
            ffma2(acc2[0][0], aa0, b2.x); ffma2(acc2[0][1], aa0, b2.y);
            ffma2(acc2[1][0], aa1, b2.x); ffma2(acc2[1][1], aa1, b2.y);
            ffma2(acc2[2][0], aa2, b2.x); ffma2(acc2[2][1], aa2, b2.y);
            ffma2(acc2[3][0], aa3, b2.x); ffma2(acc2[3][1], aa3, b2.y);
        }
        __syncthreads();
    }

    float4 bz = *(const float4*)&bias[n0 + tc * 4];
    #pragma unroll
    for (int i = 0; i < 4; i++) {
        int m = m0 + tr * 4 + i;
        int b = m >> 10;
        int t = m & (TT - 1);
        float4 v;
        unpack2(acc2[i][0], v.x, v.y);
        unpack2(acc2[i][1], v.z, v.w);
        v.x += bz.x; v.y += bz.y; v.z += bz.z; v.w += bz.w;
        *(float4*)&g_xz[((size_t)t * BB + b) * GG + n0 + tc * 4] = v;
    }
}

// ============================================================================
// Phase 2: recurrence on tensor cores via mma.sync (sm_80-class PTX, valid on
// compute_103 -- tcgen05 is rejected by this build's virtual arch).
//
// 32 clusters x 4 CTAs x 256 threads. Cluster = 8 batch rows; CTA rank owns
// 64 cells. A = W^T [128 m rows: row 2c=f_c, 2c+1=g_c][K=256], bf16 hi plane
// in REGISTERS (a_hi[16][4] per thread, 1 m16-tile per warp), lo plane in
// SMEM (ldmatrix.x4 per k-step). B = h [k=256 cells][n=8 batch] bf16 hi/lo
// planes, double-buffered; ldmatrix.x2.trans per k-step. 3 MMA passes
// (hi*hi + hi*lo + lo*hi = exact-split product) into 3 independent register
// accumulators. Gates fp32; new h split to bf16 hi/lo and broadcast to all 4
// peers via packed st.shared::cluster.b32; one barrier.cluster per step.
// ============================================================================
#define NN 4
#define SC_THREADS 256
#define ALSTR 264                   // A_lo row stride (elems): 528B, 4-bank skew
#define SA_LO 0                     // 128 x 264 x 2B = 67584
#define SB    68608                 // B: 2 stages x (hi 4KB + lo 4KB) = 16KB
#define SC_SMEM (120 * 1024)        // padded to force 1 CTA/SM

__device__ __forceinline__ void ldsm_x4(uint32_t (&r)[4], uint32_t addr) {
    asm volatile("ldmatrix.sync.aligned.m8n8.x4.shared.b16 {%0,%1,%2,%3}, [%4];"
                 : "=r"(r[0]), "=r"(r[1]), "=r"(r[2]), "=r"(r[3]) : "r"(addr));
}
__device__ __forceinline__ void ldsm_x2t(uint32_t& r0, uint32_t& r1, uint32_t addr) {
    asm volatile("ldmatrix.sync.aligned.m8n8.x2.trans.shared.b16 {%0,%1}, [%2];"
                 : "=r"(r0), "=r"(r1) : "r"(addr));
}
__device__ __forceinline__ void mma_bf16(float (&d)[4], const uint32_t (&a)[4],
                                         uint32_t b0, uint32_t b1) {
    asm volatile("mma.sync.aligned.m16n8k16.row.col.f32.bf16.bf16.f32 "
                 "{%0,%1,%2,%3}, {%4,%5,%6,%7}, {%8,%9}, {%0,%1,%2,%3};"
                 : "+f"(d[0]), "+f"(d[1]), "+f"(d[2]), "+f"(d[3])
                 : "r"(a[0]), "r"(a[1]), "r"(a[2]), "r"(a[3]), "r"(b0), "r"(b1));
}
__device__ __forceinline__ uint32_t bfpack(float lo, float hi) {
    return (uint32_t)__bfloat16_as_ushort(__float2bfloat16_rn(lo)) |
           ((uint32_t)__bfloat16_as_ushort(__float2bfloat16_rn(hi)) << 16);
}

__global__ void __launch_bounds__(SC_THREADS) __cluster_dims__(NN, 1, 1)
janet_scan_mma(const float* __restrict__ rk /* [C][2C] */) {
    extern __shared__ __align__(1024) unsigned char smem[];
    const uint32_t sbase = (uint32_t)__cvta_generic_to_shared(smem);

    const int tid  = threadIdx.x;
    const int w    = tid >> 5;          // warp 0..7 -> m rows [16w, 16w+16)
    const int lane = tid & 31;
    const int q    = lane >> 2;         // groupID 0..7
    const int cq   = lane & 3;          // threadID_in_group
    const int e    = q & 1;             // 0: f-rows / stores hi; 1: g-rows / lo

    const unsigned rank = blockIdx.x & (NN - 1);
    const unsigned tile = blockIdx.x >> 2;

    // ---- zero B stages (h0 = 0)
    for (int i = tid; i < 16384 / 4; i += SC_THREADS)
        *(uint32_t*)(smem + SB + 4 * i) = 0u;

    // ---- A_lo plane into smem (lo = w - bf16(w))
    for (int idx = tid; idx < 128 * 256; idx += SC_THREADS) {
        int m = idx & 127;
        int k = idx >> 7;
        int col = (m & 1) ? (CC + 64 * (int)rank + (m >> 1)) : (64 * (int)rank + (m >> 1));
        float v = __ldg(rk + (size_t)k * GG + col);
        float hi = __bfloat162float(__float2bfloat16_rn(v));
        *(__nv_bfloat16*)(smem + SA_LO + (size_t)(m * ALSTR + k) * 2) =
            __float2bfloat16_rn(v - hi);
    }

    // ---- A_hi fragments into registers (this warp's m16 tile, 16 k-steps)
    uint32_t a_hi[16][4];
    {
        #pragma unroll
        for (int ks = 0; ks < 16; ks++) {
            #pragma unroll
            for (int r = 0; r < 4; r++) {
                int m  = w * 16 + q + (r & 1) * 8;
                int k0 = ks * 16 + 2 * cq + (r >> 1) * 8;
                int col = (m & 1) ? (CC + 64 * (int)rank + (m >> 1))
                                  : (64 * (int)rank + (m >> 1));
                float v0 = __ldg(rk + (size_t)k0 * GG + col);
                float v1 = __ldg(rk + (size_t)(k0 + 1) * GG + col);
                a_hi[ks][r] = bfpack(v0, v1);
            }
        }
    }

    __syncthreads();
    asm volatile("barrier.cluster.arrive.aligned;" ::: "memory");
    asm volatile("barrier.cluster.wait.aligned;"   ::: "memory");

    // ---- peer B base addresses
    uint32_t peerB[NN];
    #pragma unroll
    for (int p = 0; p < NN; p++) {
        asm volatile("mapa.shared::cluster.u32 %0, %1, %2;"
                     : "=r"(peerB[p]) : "r"(sbase + SB), "r"(p));
    }

    // ---- per-lane ldmatrix addresses
    const int lj = lane >> 3, li = lane & 7;
    const uint32_t alo_lane = sbase + SA_LO +
        (uint32_t)(((w * 16 + li + (lj & 1) * 8) * ALSTR + (lj >> 1) * 8) * 2);
    const uint32_t b_lane = (uint32_t)((lane & 15) * 16);

    // ---- cell / batch mapping
    const int n0    = 2 * cq;                             // batch cols n0, n0+1
    const int cell0 = 64 * (int)rank + w * 8 + (q >> 1);  // cells cell0, cell0+4

    // xz base for this thread's own kind (f if e==0 else g)
    const float* xzp = g_xz + (e ? CC : 0) + (size_t)(tile * 8 + n0) * GG + cell0;
    float pf[2][2];
    pf[0][0] = __ldcs(xzp);      pf[0][1] = __ldcs(xzp + GG);
    pf[1][0] = __ldcs(xzp + 4);  pf[1][1] = __ldcs(xzp + GG + 4);

    float cst[2][2] = {{0.f, 0.f}, {0.f, 0.f}};

    for (int t = 0; t < TT; t++) {
        const int cur = t & 1;
        const uint32_t bst = sbase + SB + (uint32_t)cur * 8192u;

        float d[3][4];
        #pragma unroll
        for (int pl = 0; pl < 3; pl++)
            #pragma unroll
            for (int i = 0; i < 4; i++) d[pl][i] = 0.0f;

        #pragma unroll
        for (int ks = 0; ks < 16; ks++) {
            uint32_t bh0, bh1, bl0, bl1, alo[4];
            ldsm_x2t(bh0, bh1, bst + (uint32_t)ks * 256u + b_lane);
            ldsm_x2t(bl0, bl1, bst + 4096u + (uint32_t)ks * 256u + b_lane);
            ldsm_x4(alo, alo_lane + (uint32_t)(ks * 32));
            mma_bf16(d[0], a_hi[ks], bh0, bh1);   // A_hi * B_hi
            mma_bf16(d[1], a_hi[ks], bl0, bl1);   // A_hi * B_lo
            mma_bf16(d[2], alo,      bh0, bh1);   // A_lo * B_hi
        }

        // z (own kind) = MMA sum + own-kind xz
        float zo[2][2];
        #pragma unroll
        for (int rr = 0; rr < 2; rr++)
            #pragma unroll
            for (int col = 0; col < 2; col++)
                zo[rr][col] = d[0][rr * 2 + col] + d[1][rr * 2 + col] +
                              d[2][rr * 2 + col] + pf[rr][col];

        // pair f/g via quad exchange (q ^ 1)
        float zx[2][2];
        #pragma unroll
        for (int rr = 0; rr < 2; rr++)
            #pragma unroll
            for (int col = 0; col < 2; col++)
                zx[rr][col] = __shfl_xor_sync(0xffffffffu, zo[rr][col], 4);

        const uint32_t st_off = (uint32_t)(cur ^ 1) * 8192u + (uint32_t)e * 4096u +
                                (uint32_t)(n0 * 2);
        #pragma unroll
        for (int rr = 0; rr < 2; rr++) {
            float v0, v1;
            #pragma unroll
            for (int col = 0; col < 2; col++) {
                float zf = e ? zx[rr][col] : zo[rr][col];
                float zg = e ? zo[rr][col] : zx[rr][col];
                float f = fast_sigmoid(zf);
                float g = 2.0f * fast_sigmoid(2.0f * zg) - 1.0f;  // tanh
                float c = f * cst[rr][col] + (1.0f - f) * g;
                cst[rr][col] = c;
                float out = c;
                if (e) {  // lo plane: residual after bf16 hi
                    out = c - __bfloat162float(__float2bfloat16_rn(c));
                }
                if (col == 0) v0 = out; else v1 = out;
            }
            uint32_t pk = bfpack(v0, v1);
            uint32_t off = st_off + (uint32_t)((cell0 + rr * 4) * 16);
            #pragma unroll
            for (int p = 0; p < NN; p++) {
                asm volatile("st.shared::cluster.b32 [%0], %1;"
                             :: "r"(peerB[p] + off), "r"(pk) : "memory");
            }
        }

        // prefetch next step's xz
        if (t + 1 < TT) xzp += (size_t)BB * GG;
        pf[0][0] = __ldcs(xzp);      pf[0][1] = __ldcs(xzp + GG);
        pf[1][0] = __ldcs(xzp + 4);  pf[1][1] = __ldcs(xzp + GG + 4);

        asm volatile("barrier.cluster.arrive.aligned;" ::: "memory");
        asm volatile("barrier.cluster.wait.aligned;"   ::: "memory");
    }

    // ---- final h (even quads hold canonical values)
    if (e == 0) {
        #pragma unroll
        for (int rr = 0; rr < 2; rr++)
            #pragma unroll
            for (int col = 0; col < 2; col++)
                g_h[((int)tile * 8 + n0 + col) * CC + cell0 + rr * 4] = cst[rr][col];
    }
}

// ============================================================================
// Phase 3: out = h_final @ dense_w + dense_b   (256x256 @ 256x10)
// ============================================================================
__global__ void __launch_bounds__(32) dense_kernel(const float* __restrict__ dw,
                                                   const float* __restrict__ db,
                                                   float* __restrict__ out) {
    int b = blockIdx.x;
    int o = threadIdx.x;
    if (o < OO) {
        float acc = 0.0f;
        #pragma unroll 8
        for (int c = 0; c < CC; c++) {
            acc += g_h[b * CC + c] * dw[c * OO + o];
        }
        out[b * OO + o] = acc + db[o];
    }
}

// ============================================================================
extern "C" void kernel_launch(void* const* d_in, const int* in_sizes, int n_in,
                              void* d_out, int out_size) {
    const float* x  = (const float*)d_in[0];
    const float* wk = (const float*)d_in[1];
    const float* rk = (const float*)d_in[2];
    const float* rb = (const float*)d_in[3];
    const float* dw = (const float*)d_in[4];
    const float* db = (const float*)d_in[5];
    float* out = (float*)d_out;

    // Phase 1: input projection GEMM
    dim3 g1(GG / 64, (BB * TT) / 64);
    xz_gemm_kernel<<<g1, 256>>>(x, wk, rb);

    // Phase 2: mma.sync recurrence (dynamic smem padded to force 1 CTA/SM)
    cudaFuncSetAttribute(janet_scan_mma, cudaFuncAttributeMaxDynamicSharedMemorySize, SC_SMEM);
    janet_scan_mma<<<32 * NN, SC_THREADS, SC_SMEM>>>(rk);

    // Phase 3: final dense
    dense_kernel<<<BB, 32>>>(dw, db, out);
}

// round 13
// speedup vs baseline: 4.6778x; 1.2282x over previous
#include <cuda_runtime.h>
#include <cuda_bf16.h>
#include <cstdint>
#include <cstddef>

// Problem dims
#define BB 256
#define TT 1024
#define II 128
#define CC 256
#define GG 512   // 2C
#define OO 10

// Scratch (static device globals -- allocation-free kernel_launch)
__device__ float g_xz[(size_t)TT * BB * GG];   // [t][b][g]  (512 MB)
__device__ float g_h[BB * CC];                 // final hidden state

__device__ __forceinline__ float fast_sigmoid(float x) {
    return __fdividef(1.0f, 1.0f + __expf(-x));
}

// ---- shared mma.sync helpers (sm_80-class PTX; valid on compute_103) ----
__device__ __forceinline__ void ldsm_x4(uint32_t (&r)[4], uint32_t addr) {
    asm volatile("ldmatrix.sync.aligned.m8n8.x4.shared.b16 {%0,%1,%2,%3}, [%4];"
                 : "=r"(r[0]), "=r"(r[1]), "=r"(r[2]), "=r"(r[3]) : "r"(addr));
}
__device__ __forceinline__ void ldsm_x2t(uint32_t& r0, uint32_t& r1, uint32_t addr) {
    asm volatile("ldmatrix.sync.aligned.m8n8.x2.trans.shared.b16 {%0,%1}, [%2];"
                 : "=r"(r0), "=r"(r1) : "r"(addr));
}
__device__ __forceinline__ void mma_bf16(float (&d)[4], const uint32_t (&a)[4],
                                         uint32_t b0, uint32_t b1) {
    asm volatile("mma.sync.aligned.m16n8k16.row.col.f32.bf16.bf16.f32 "
                 "{%0,%1,%2,%3}, {%4,%5,%6,%7}, {%8,%9}, {%0,%1,%2,%3};"
                 : "+f"(d[0]), "+f"(d[1]), "+f"(d[2]), "+f"(d[3])
                 : "r"(a[0]), "r"(a[1]), "r"(a[2]), "r"(a[3]), "r"(b0), "r"(b1));
}
__device__ __forceinline__ uint32_t bfpack(float lo, float hi) {
    return (uint32_t)__bfloat16_as_ushort(__float2bfloat16_rn(lo)) |
           ((uint32_t)__bfloat16_as_ushort(__float2bfloat16_rn(hi)) << 16);
}
__device__ __forceinline__ void bfsplit(float v, __nv_bfloat16& h, __nv_bfloat16& l) {
    h = __float2bfloat16_rn(v);
    l = __float2bfloat16_rn(v - __bfloat162float(h));
}

// ============================================================================
// Phase 1: xz = x @ kernel + bias on TENSOR CORES.
// M=262144, N=512, K=128. CTA tile 128x128, K chunks of 64. x and w split into
// bf16 hi/lo planes in SMEM; 3 MMA passes (hi*hi + hi*lo + lo*hi, exact-split)
// into one fp32 accumulator. 8 warps: warp_m = w>>1 (m32), warp_n = w&1 (n64).
// ============================================================================
#define XG_THREADS 256
// smem layout (bytes): A planes 128 rows x 72 bf16 (144B, 16B-phase skew);
// B planes 64 rows x 136 bf16 (272B).
#define XG_AXH 0
#define XG_AXL 18432
#define XG_BWH 36864
#define XG_BWL 54272
#define XG_SMEM 71680

__global__ void __launch_bounds__(XG_THREADS, 2)
xz_gemm_tc(const float* __restrict__ x, const float* __restrict__ wk,
           const float* __restrict__ bias) {
    extern __shared__ __align__(1024) unsigned char smem[];
    const uint32_t sbase = (uint32_t)__cvta_generic_to_shared(smem);

    const int tid  = threadIdx.x;
    const int w    = tid >> 5;
    const int lane = tid & 31;
    const int warp_m = w >> 1;          // 0..3 -> m rows [32*warp_m, +32)
    const int warp_n = w & 1;           // 0..1 -> n cols [64*warp_n, +64)
    const int m0 = blockIdx.y * 128;
    const int n0 = blockIdx.x * 128;

    // ldmatrix lane addresses
    const int li = lane & 7, lj = lane >> 3;
    const uint32_t aAddrH = sbase + XG_AXH +
        (uint32_t)((warp_m * 32 + li + (lj & 1) * 8) * 144 + ((lj >> 1) * 8) * 2);
    const uint32_t aAddrL = aAddrH + (XG_AXL - XG_AXH);
    const uint32_t bAddrH = sbase + XG_BWH +
        (uint32_t)((lane & 15) * 272 + (warp_n * 64) * 2);
    const uint32_t bAddrL = bAddrH + (XG_BWL - XG_BWH);

    float d[2][8][4];
    #pragma unroll
    for (int mt = 0; mt < 2; mt++)
        #pragma unroll
        for (int nt = 0; nt < 8; nt++)
            #pragma unroll
            for (int i = 0; i < 4; i++) d[mt][nt][i] = 0.0f;

    #pragma unroll
    for (int kc = 0; kc < 2; kc++) {
        // ---- load + split x tile [128 m][64 k]
        #pragma unroll
        for (int i = 0; i < 8; i++) {
            int idx = tid + i * 256;
            int r = idx >> 4, c4 = (idx & 15) * 4;
            float4 v = *(const float4*)(x + (size_t)(m0 + r) * II + kc * 64 + c4);
            __nv_bfloat16 h0, l0, h1, l1, h2, l2, h3, l3;
            bfsplit(v.x, h0, l0); bfsplit(v.y, h1, l1);
            bfsplit(v.z, h2, l2); bfsplit(v.w, h3, l3);
            unsigned char* ph = smem + XG_AXH + r * 144 + c4 * 2;
            unsigned char* pl = smem + XG_AXL + r * 144 + c4 * 2;
            *(__nv_bfloat162*)(ph)     = __halves2bfloat162(h0, h1);
            *(__nv_bfloat162*)(ph + 4) = __halves2bfloat162(h2, h3);
            *(__nv_bfloat162*)(pl)     = __halves2bfloat162(l0, l1);
            *(__nv_bfloat162*)(pl + 4) = __halves2bfloat162(l2, l3);
        }
        // ---- load + split w tile [64 k][128 n]
        #pragma unroll
        for (int i = 0; i < 8; i++) {
            int idx = tid + i * 256;
            int kk = idx >> 5, c4 = (idx & 31) * 4;
            float4 v = *(const float4*)(wk + (size_t)(kc * 64 + kk) * GG + n0 + c4);
            __nv_bfloat16 h0, l0, h1, l1, h2, l2, h3, l3;
            bfsplit(v.x, h0, l0); bfsplit(v.y, h1, l1);
            bfsplit(v.z, h2, l2); bfsplit(v.w, h3, l3);
            unsigned char* ph = smem + XG_BWH + kk * 272 + c4 * 2;
            unsigned char* pl = smem + XG_BWL + kk * 272 + c4 * 2;
            *(__nv_bfloat162*)(ph)     = __halves2bfloat162(h0, h1);
            *(__nv_bfloat162*)(ph + 4) = __halves2bfloat162(h2, h3);
            *(__nv_bfloat162*)(pl)     = __halves2bfloat162(l0, l1);
            *(__nv_bfloat162*)(pl + 4) = __halves2bfloat162(l2, l3);
        }
        __syncthreads();

        #pragma unroll
        for (int ks = 0; ks < 4; ks++) {
            uint32_t ah[2][4], al[2][4];
            #pragma unroll
            for (int mt = 0; mt < 2; mt++) {
                ldsm_x4(ah[mt], aAddrH + (uint32_t)(mt * 2304 + ks * 32));
                ldsm_x4(al[mt], aAddrL + (uint32_t)(mt * 2304 + ks * 32));
            }
            #pragma unroll
            for (int nt = 0; nt < 8; nt++) {
                uint32_t bh0, bh1, bl0, bl1;
                ldsm_x2t(bh0, bh1, bAddrH + (uint32_t)(ks * 4352 + nt * 16));
                ldsm_x2t(bl0, bl1, bAddrL + (uint32_t)(ks * 4352 + nt * 16));
                #pragma unroll
                for (int mt = 0; mt < 2; mt++) {
                    mma_bf16(d[mt][nt], ah[mt], bh0, bh1);   // hi*hi
                    mma_bf16(d[mt][nt], ah[mt], bl0, bl1);   // hi*lo
                    mma_bf16(d[mt][nt], al[mt], bh0, bh1);   // lo*hi
                }
            }
        }
        __syncthreads();
    }

    // ---- epilogue: + bias, store fp32 to g_xz[t][b][g]
    const int q = lane >> 2, tig = lane & 3;
    #pragma unroll
    for (int nt = 0; nt < 8; nt++) {
        const int col = n0 + warp_n * 64 + nt * 8 + 2 * tig;
        float2 bz = *(const float2*)&bias[col];
        #pragma unroll
        for (int mt = 0; mt < 2; mt++) {
            int mrow = m0 + warp_m * 32 + mt * 16 + q;
            #pragma unroll
            for (int half = 0; half < 2; half++) {
                int m = mrow + half * 8;
                int b = m >> 10, t = m & (TT - 1);
                float2 v;
                v.x = d[mt][nt][2 * half + 0] + bz.x;
                v.y = d[mt][nt][2 * half + 1] + bz.y;
                *(float2*)&g_xz[((size_t)t * BB + b) * GG + col] = v;
            }
        }
    }
}

// ============================================================================
// Phase 2: recurrence on tensor cores via mma.sync (UNCHANGED from the proven
// 2731us kernel). 32 clusters x 4 CTAs x 256 threads; A_hi in regs, A_lo in
// smem, B = h bf16 hi/lo double-buffered, 3-pass exact split, DSMEM broadcast
// + one barrier.cluster per step.
// ============================================================================
#define NN 4
#define SC_THREADS 256
#define ALSTR 264
#define SA_LO 0
#define SB    68608
#define SC_SMEM (120 * 1024)

__global__ void __launch_bounds__(SC_THREADS) __cluster_dims__(NN, 1, 1)
janet_scan_mma(const float* __restrict__ rk /* [C][2C] */) {
    extern __shared__ __align__(1024) unsigned char smem[];
    const uint32_t sbase = (uint32_t)__cvta_generic_to_shared(smem);

    const int tid  = threadIdx.x;
    const int w    = tid >> 5;
    const int lane = tid & 31;
    const int q    = lane >> 2;
    const int cq   = lane & 3;
    const int e    = q & 1;

    const unsigned rank = blockIdx.x & (NN - 1);
    const unsigned tile = blockIdx.x >> 2;

    for (int i = tid; i < 16384 / 4; i += SC_THREADS)
        *(uint32_t*)(smem + SB + 4 * i) = 0u;

    for (int idx = tid; idx < 128 * 256; idx += SC_THREADS) {
        int m = idx & 127;
        int k = idx >> 7;
        int col = (m & 1) ? (CC + 64 * (int)rank + (m >> 1)) : (64 * (int)rank + (m >> 1));
        float v = __ldg(rk + (size_t)k * GG + col);
        float hi = __bfloat162float(__float2bfloat16_rn(v));
        *(__nv_bfloat16*)(smem + SA_LO + (size_t)(m * ALSTR + k) * 2) =
            __float2bfloat16_rn(v - hi);
    }

    uint32_t a_hi[16][4];
    {
        #pragma unroll
        for (int ks = 0; ks < 16; ks++) {
            #pragma unroll
            for (int r = 0; r < 4; r++) {
                int m  = w * 16 + q + (r & 1) * 8;
                int k0 = ks * 16 + 2 * cq + (r >> 1) * 8;
                int col = (m & 1) ? (CC + 64 * (int)rank + (m >> 1))
                                  : (64 * (int)rank + (m >> 1));
                float v0 = __ldg(rk + (size_t)k0 * GG + col);
                float v1 = __ldg(rk + (size_t)(k0 + 1) * GG + col);
                a_hi[ks][r] = bfpack(v0, v1);
            }
        }
    }

    __syncthreads();
    asm volatile("barrier.cluster.arrive.aligned;" ::: "memory");
    asm volatile("barrier.cluster.wait.aligned;"   ::: "memory");

    uint32_t peerB[NN];
    #pragma unroll
    for (int p = 0; p < NN; p++) {
        asm volatile("mapa.shared::cluster.u32 %0, %1, %2;"
                     : "=r"(peerB[p]) : "r"(sbase + SB), "r"(p));
    }

    const int lj = lane >> 3, li = lane & 7;
    const uint32_t alo_lane = sbase + SA_LO +
        (uint32_t)(((w * 16 + li + (lj & 1) * 8) * ALSTR + (lj >> 1) * 8) * 2);
    const uint32_t b_lane = (uint32_t)((lane & 15) * 16);

    const int n0    = 2 * cq;
    const int cell0 = 64 * (int)rank + w * 8 + (q >> 1);

    const float* xzp = g_xz + (e ? CC : 0) + (size_t)(tile * 8 + n0) * GG + cell0;
    float pf[2][2];
    pf[0][0] = __ldcs(xzp);      pf[0][1] = __ldcs(xzp + GG);
    pf[1][0] = __ldcs(xzp + 4);  pf[1][1] = __ldcs(xzp + GG + 4);

    float cst[2][2] = {{0.f, 0.f}, {0.f, 0.f}};

    for (int t = 0; t < TT; t++) {
        const int cur = t & 1;
        const uint32_t bst = sbase + SB + (uint32_t)cur * 8192u;

        float d[3][4];
        #pragma unroll
        for (int pl = 0; pl < 3; pl++)
            #pragma unroll
            for (int i = 0; i < 4; i++) d[pl][i] = 0.0f;

        #pragma unroll
        for (int ks = 0; ks < 16; ks++) {
            uint32_t bh0, bh1, bl0, bl1, alo[4];
            ldsm_x2t(bh0, bh1, bst + (uint32_t)ks * 256u + b_lane);
            ldsm_x2t(bl0, bl1, bst + 4096u + (uint32_t)ks * 256u + b_lane);
            ldsm_x4(alo, alo_lane + (uint32_t)(ks * 32));
            mma_bf16(d[0], a_hi[ks], bh0, bh1);
            mma_bf16(d[1], a_hi[ks], bl0, bl1);
            mma_bf16(d[2], alo,      bh0, bh1);
        }

        float zo[2][2];
        #pragma unroll
        for (int rr = 0; rr < 2; rr++)
            #pragma unroll
            for (int col = 0; col < 2; col++)
                zo[rr][col] = d[0][rr * 2 + col] + d[1][rr * 2 + col] +
                              d[2][rr * 2 + col] + pf[rr][col];

        float zx[2][2];
        #pragma unroll
        for (int rr = 0; rr < 2; rr++)
            #pragma unroll
            for (int col = 0; col < 2; col++)
                zx[rr][col] = __shfl_xor_sync(0xffffffffu, zo[rr][col], 4);

        const uint32_t st_off = (uint32_t)(cur ^ 1) * 8192u + (uint32_t)e * 4096u +
                                (uint32_t)(n0 * 2);
        #pragma unroll
        for (int rr = 0; rr < 2; rr++) {
            float v0, v1;
            #pragma unroll
            for (int col = 0; col < 2; col++) {
                float zf = e ? zx[rr][col] : zo[rr][col];
                float zg = e ? zo[rr][col] : zx[rr][col];
                float f = fast_sigmoid(zf);
                float g = 2.0f * fast_sigmoid(2.0f * zg) - 1.0f;
                float c = f * cst[rr][col] + (1.0f - f) * g;
                cst[rr][col] = c;
                float out = c;
                if (e) {
                    out = c - __bfloat162float(__float2bfloat16_rn(c));
                }
                if (col == 0) v0 = out; else v1 = out;
            }
            uint32_t pk = bfpack(v0, v1);
            uint32_t off = st_off + (uint32_t)((cell0 + rr * 4) * 16);
            #pragma unroll
            for (int p = 0; p < NN; p++) {
                asm volatile("st.shared::cluster.b32 [%0], %1;"
                             :: "r"(peerB[p] + off), "r"(pk) : "memory");
            }
        }

        if (t + 1 < TT) xzp += (size_t)BB * GG;
        pf[0][0] = __ldcs(xzp);      pf[0][1] = __ldcs(xzp + GG);
        pf[1][0] = __ldcs(xzp + 4);  pf[1][1] = __ldcs(xzp + GG + 4);

        asm volatile("barrier.cluster.arrive.aligned;" ::: "memory");
        asm volatile("barrier.cluster.wait.aligned;"   ::: "memory");
    }

    if (e == 0) {
        #pragma unroll
        for (int rr = 0; rr < 2; rr++)
            #pragma unroll
            for (int col = 0; col < 2; col++)
                g_h[((int)tile * 8 + n0 + col) * CC + cell0 + rr * 4] = cst[rr][col];
    }
}

// ============================================================================
// Phase 3: out = h_final @ dense_w + dense_b   (256x256 @ 256x10)
// ============================================================================
__global__ void __launch_bounds__(32) dense_kernel(const float* __restrict__ dw,
                                                   const float* __restrict__ db,
                                                   float* __restrict__ out) {
    int b = blockIdx.x;
    int o = threadIdx.x;
    if (o < OO) {
        float acc = 0.0f;
        #pragma unroll 8
        for (int c = 0; c < CC; c++) {
            acc += g_h[b * CC + c] * dw[c * OO + o];
        }
        out[b * OO + o] = acc + db[o];
    }
}

// ============================================================================
extern "C" void kernel_launch(void* const* d_in, const int* in_sizes, int n_in,
                              void* d_out, int out_size) {
    const float* x  = (const float*)d_in[0];
    const float* wk = (const float*)d_in[1];
    const float* rk = (const float*)d_in[2];
    const float* rb = (const float*)d_in[3];
    const float* dw = (const float*)d_in[4];
    const float* db = (const float*)d_in[5];
    float* out = (float*)d_out;

    // Phase 1: input projection GEMM on tensor cores
    cudaFuncSetAttribute(xz_gemm_tc, cudaFuncAttributeMaxDynamicSharedMemorySize, XG_SMEM);
    xz_gemm_tc<<<dim3(GG / 128, (BB * TT) / 128), XG_THREADS, XG_SMEM>>>(x, wk, rb);

    // Phase 2: mma.sync recurrence (proven; unchanged)
    cudaFuncSetAttribute(janet_scan_mma, cudaFuncAttributeMaxDynamicSharedMemorySize, SC_SMEM);
    janet_scan_mma<<<32 * NN, SC_THREADS, SC_SMEM>>>(rk);

    // Phase 3: final dense
    dense_kernel<<<BB, 32>>>(dw, db, out);
}

// round 14
// speedup vs baseline: 7.9978x; 1.7097x over previous
#include <cuda_runtime.h>
#include <cuda_bf16.h>
#include <cuda_fp16.h>
#include <cstdint>
#include <cstddef>

// Problem dims
#define BB 256
#define TT 1024
#define II 128
#define CC 256
#define GG 512   // 2C
#define OO 10

// Scratch (static device globals -- allocation-free kernel_launch)
__device__ float g_xz[(size_t)TT * BB * GG];   // [t][b][g]  (512 MB)
__device__ float g_h[BB * CC];                 // final hidden state

__device__ __forceinline__ float fast_sigmoid(float x) {
    return __fdividef(1.0f, 1.0f + __expf(-x));
}

// ---- shared mma.sync helpers (sm_80-class PTX; valid on compute_103) ----
__device__ __forceinline__ void ldsm_x4(uint32_t (&r)[4], uint32_t addr) {
    asm volatile("ldmatrix.sync.aligned.m8n8.x4.shared.b16 {%0,%1,%2,%3}, [%4];"
                 : "=r"(r[0]), "=r"(r[1]), "=r"(r[2]), "=r"(r[3]) : "r"(addr));
}
__device__ __forceinline__ void ldsm_x2t(uint32_t& r0, uint32_t& r1, uint32_t addr) {
    asm volatile("ldmatrix.sync.aligned.m8n8.x2.trans.shared.b16 {%0,%1}, [%2];"
                 : "=r"(r0), "=r"(r1) : "r"(addr));
}
__device__ __forceinline__ void mma_bf16(float (&d)[4], const uint32_t (&a)[4],
                                         uint32_t b0, uint32_t b1) {
    asm volatile("mma.sync.aligned.m16n8k16.row.col.f32.bf16.bf16.f32 "
                 "{%0,%1,%2,%3}, {%4,%5,%6,%7}, {%8,%9}, {%0,%1,%2,%3};"
                 : "+f"(d[0]), "+f"(d[1]), "+f"(d[2]), "+f"(d[3])
                 : "r"(a[0]), "r"(a[1]), "r"(a[2]), "r"(a[3]), "r"(b0), "r"(b1));
}
__device__ __forceinline__ void mma_f16(float (&d)[4], const uint32_t (&a)[4],
                                        uint32_t b0, uint32_t b1) {
    asm volatile("mma.sync.aligned.m16n8k16.row.col.f32.f16.f16.f32 "
                 "{%0,%1,%2,%3}, {%4,%5,%6,%7}, {%8,%9}, {%0,%1,%2,%3};"
                 : "+f"(d[0]), "+f"(d[1]), "+f"(d[2]), "+f"(d[3])
                 : "r"(a[0]), "r"(a[1]), "r"(a[2]), "r"(a[3]), "r"(b0), "r"(b1));
}
__device__ __forceinline__ void bfsplit(float v, __nv_bfloat16& h, __nv_bfloat16& l) {
    h = __float2bfloat16_rn(v);
    l = __float2bfloat16_rn(v - __bfloat162float(h));
}
__device__ __forceinline__ uint32_t hpack(__half a, __half b) {
    return (uint32_t)__half_as_ushort(a) | ((uint32_t)__half_as_ushort(b) << 16);
}

// ============================================================================
// Phase 1: xz GEMM on tensor cores (proven 394us; unchanged this round)
// ============================================================================
#define XG_THREADS 256
#define XG_AXH 0
#define XG_AXL 18432
#define XG_BWH 36864
#define XG_BWL 54272
#define XG_SMEM 71680

__global__ void __launch_bounds__(XG_THREADS, 2)
xz_gemm_tc(const float* __restrict__ x, const float* __restrict__ wk,
           const float* __restrict__ bias) {
    extern __shared__ __align__(1024) unsigned char smem[];
    const uint32_t sbase = (uint32_t)__cvta_generic_to_shared(smem);

    const int tid  = threadIdx.x;
    const int w    = tid >> 5;
    const int lane = tid & 31;
    const int warp_m = w >> 1;
    const int warp_n = w & 1;
    const int m0 = blockIdx.y * 128;
    const int n0 = blockIdx.x * 128;

    const int li = lane & 7, lj = lane >> 3;
    const uint32_t aAddrH = sbase + XG_AXH +
        (uint32_t)((warp_m * 32 + li + (lj & 1) * 8) * 144 + ((lj >> 1) * 8) * 2);
    const uint32_t aAddrL = aAddrH + (XG_AXL - XG_AXH);
    const uint32_t bAddrH = sbase + XG_BWH +
        (uint32_t)((lane & 15) * 272 + (warp_n * 64) * 2);
    const uint32_t bAddrL = bAddrH + (XG_BWL - XG_BWH);

    float d[2][8][4];
    #pragma unroll
    for (int mt = 0; mt < 2; mt++)
        #pragma unroll
        for (int nt = 0; nt < 8; nt++)
            #pragma unroll
            for (int i = 0; i < 4; i++) d[mt][nt][i] = 0.0f;

    #pragma unroll
    for (int kc = 0; kc < 2; kc++) {
        #pragma unroll
        for (int i = 0; i < 8; i++) {
            int idx = tid + i * 256;
            int r = idx >> 4, c4 = (idx & 15) * 4;
            float4 v = *(const float4*)(x + (size_t)(m0 + r) * II + kc * 64 + c4);
            __nv_bfloat16 h0, l0, h1, l1, h2, l2, h3, l3;
            bfsplit(v.x, h0, l0); bfsplit(v.y, h1, l1);
            bfsplit(v.z, h2, l2); bfsplit(v.w, h3, l3);
            unsigned char* ph = smem + XG_AXH + r * 144 + c4 * 2;
            unsigned char* pl = smem + XG_AXL + r * 144 + c4 * 2;
            *(__nv_bfloat162*)(ph)     = __halves2bfloat162(h0, h1);
            *(__nv_bfloat162*)(ph + 4) = __halves2bfloat162(h2, h3);
            *(__nv_bfloat162*)(pl)     = __halves2bfloat162(l0, l1);
            *(__nv_bfloat162*)(pl + 4) = __halves2bfloat162(l2, l3);
        }
        #pragma unroll
        for (int i = 0; i < 8; i++) {
            int idx = tid + i * 256;
            int kk = idx >> 5, c4 = (idx & 31) * 4;
            float4 v = *(const float4*)(wk + (size_t)(kc * 64 + kk) * GG + n0 + c4);
            __nv_bfloat16 h0, l0, h1, l1, h2, l2, h3, l3;
            bfsplit(v.x, h0, l0); bfsplit(v.y, h1, l1);
            bfsplit(v.z, h2, l2); bfsplit(v.w, h3, l3);
            unsigned char* ph = smem + XG_BWH + kk * 272 + c4 * 2;
            unsigned char* pl = smem + XG_BWL + kk * 272 + c4 * 2;
            *(__nv_bfloat162*)(ph)     = __halves2bfloat162(h0, h1);
            *(__nv_bfloat162*)(ph + 4) = __halves2bfloat162(h2, h3);
            *(__nv_bfloat162*)(pl)     = __halves2bfloat162(l0, l1);
            *(__nv_bfloat162*)(pl + 4) = __halves2bfloat162(l2, l3);
        }
        __syncthreads();

        #pragma unroll
        for (int ks = 0; ks < 4; ks++) {
            uint32_t ah[2][4], al[2][4];
            #pragma unroll
            for (int mt = 0; mt < 2; mt++) {
                ldsm_x4(ah[mt], aAddrH + (uint32_t)(mt * 2304 + ks * 32));
                ldsm_x4(al[mt], aAddrL + (uint32_t)(mt * 2304 + ks * 32));
            }
            #pragma unroll
            for (int nt = 0; nt < 8; nt++) {
                uint32_t bh0, bh1, bl0, bl1;
                ldsm_x2t(bh0, bh1, bAddrH + (uint32_t)(ks * 4352 + nt * 16));
                ldsm_x2t(bl0, bl1, bAddrL + (uint32_t)(ks * 4352 + nt * 16));
                #pragma unroll
                for (int mt = 0; mt < 2; mt++) {
                    mma_bf16(d[mt][nt], ah[mt], bh0, bh1);
                    mma_bf16(d[mt][nt], ah[mt], bl0, bl1);
                    mma_bf16(d[mt][nt], al[mt], bh0, bh1);
                }
            }
        }
        __syncthreads();
    }

    const int q = lane >> 2, tig = lane & 3;
    #pragma unroll
    for (int nt = 0; nt < 8; nt++) {
        const int col = n0 + warp_n * 64 + nt * 8 + 2 * tig;
        float2 bz = *(const float2*)&bias[col];
        #pragma unroll
        for (int mt = 0; mt < 2; mt++) {
            int mrow = m0 + warp_m * 32 + mt * 16 + q;
            #pragma unroll
            for (int half = 0; half < 2; half++) {
                int m = mrow + half * 8;
                int b = m >> 10, t = m & (TT - 1);
                float2 v;
                v.x = d[mt][nt][2 * half + 0] + bz.x;
                v.y = d[mt][nt][2 * half + 1] + bz.y;
                *(float2*)&g_xz[((size_t)t * BB + b) * GG + col] = v;
            }
        }
    }
}

// ============================================================================
// Phase 2: recurrence, fp16 2-pass (W exact as fp16 hi + fp16 lo*2048 in
// REGISTERS; h single fp16 plane), st.async + mbarrier complete_tx sync.
//
// 32 clusters x 4 CTAs x 256 threads. CTA rank owns 64 cells (M=128 rows:
// 2c=f, 2c+1=g), K=256, N=8 batch. Per step per warp: 16 ldsm.x2.trans +
// 32 HMMA (2 passes x 16 ks, 4 accumulator chains). h stores go to all 4
// peers via st.async.b32 carrying complete_tx to the peer's stage mbarrier
// (expect_tx 4096 B/step); no barrier.cluster in the loop. Backpressure is
// implicit: a peer's stores depend on its MMAs which depend on its ldsm reads.
// ============================================================================
#define NN 4
#define SC_THREADS 256
#define SC_STAGE 4096                 // 256 k-rows x 8 n x fp16

__global__ void __launch_bounds__(SC_THREADS, 1) __cluster_dims__(NN, 1, 1)
janet_scan_mma(const float* __restrict__ rk /* [C][2C] */) {
    __shared__ __align__(1024) unsigned char smem[2 * SC_STAGE + 16];
    const uint32_t sbase = (uint32_t)__cvta_generic_to_shared(smem);
    const uint32_t mb_base = sbase + 2 * SC_STAGE;      // mb[0], mb[1] (8B each)

    const int tid  = threadIdx.x;
    const int w    = tid >> 5;
    const int lane = tid & 31;
    const int q    = lane >> 2;
    const int cq   = lane & 3;
    const int e    = q & 1;

    const unsigned rank = blockIdx.x & (NN - 1);
    const unsigned tile = blockIdx.x >> 2;

    // ---- zero both h stages (h0 = 0)
    for (int i = tid; i < 2 * SC_STAGE / 4; i += SC_THREADS)
        *(uint32_t*)(smem + 4 * i) = 0u;

    // ---- W fragments into registers: hi fp16 + (lo*2048) fp16 (exact split)
    uint32_t a_hi[16][4], a_lo[16][4];
    #pragma unroll
    for (int ks = 0; ks < 16; ks++) {
        #pragma unroll
        for (int r = 0; r < 4; r++) {
            int m  = w * 16 + q + (r & 1) * 8;
            int k0 = ks * 16 + 2 * cq + (r >> 1) * 8;
            int col = (m & 1) ? (CC + 64 * (int)rank + (m >> 1))
                              : (64 * (int)rank + (m >> 1));
            float v0 = __ldg(rk + (size_t)k0 * GG + col);
            float v1 = __ldg(rk + (size_t)(k0 + 1) * GG + col);
            __half h0 = __float2half_rn(v0);
            __half h1 = __float2half_rn(v1);
            __half l0 = __float2half_rn((v0 - __half2float(h0)) * 2048.0f);
            __half l1 = __float2half_rn((v1 - __half2float(h1)) * 2048.0f);
            a_hi[ks][r] = hpack(h0, h1);
            a_lo[ks][r] = hpack(l0, l1);
        }
    }

    // ---- mbarrier init + pre-arm both stages (count 1; expect 4096 B)
    if (tid == 0) {
        asm volatile("mbarrier.init.shared.b64 [%0], 1;" :: "r"(mb_base) : "memory");
        asm volatile("mbarrier.init.shared.b64 [%0], 1;" :: "r"(mb_base + 8) : "memory");
        asm volatile("mbarrier.arrive.expect_tx.shared.b64 _, [%0], %1;"
                     :: "r"(mb_base), "r"(4096u) : "memory");
        asm volatile("mbarrier.arrive.expect_tx.shared.b64 _, [%0], %1;"
                     :: "r"(mb_base + 8), "r"(4096u) : "memory");
    }
    __syncthreads();
    asm volatile("barrier.cluster.arrive.aligned;" ::: "memory");
    asm volatile("barrier.cluster.wait.aligned;"   ::: "memory");

    // ---- peer addresses (B stages + mbarriers)
    uint32_t peerB[NN], peerMB[NN];
    #pragma unroll
    for (int p = 0; p < NN; p++) {
        asm volatile("mapa.shared::cluster.u32 %0, %1, %2;"
                     : "=r"(peerB[p]) : "r"(sbase), "r"(p));
        asm volatile("mapa.shared::cluster.u32 %0, %1, %2;"
                     : "=r"(peerMB[p]) : "r"(mb_base), "r"(p));
    }

    const uint32_t b_lane = (uint32_t)((lane & 15) * 16);
    const int n0    = 2 * cq;
    const int cell0 = 64 * (int)rank + w * 8 + (q >> 1);

    const float* xzp = g_xz + (e ? CC : 0) + (size_t)(tile * 8 + n0) * GG + cell0;
    float pf[2][2];
    pf[0][0] = __ldcs(xzp);      pf[0][1] = __ldcs(xzp + GG);
    pf[1][0] = __ldcs(xzp + 4);  pf[1][1] = __ldcs(xzp + GG + 4);

    float cst[2][2] = {{0.f, 0.f}, {0.f, 0.f}};
    uint32_t p0 = 0, p1 = 0;    // mbarrier phase parities

    for (int t = 0; t < TT; t++) {
        const int cur = t & 1;

        // ---- wait for this stage's h (skip t=0: stage 0 pre-zeroed locally)
        if (t > 0) {
            const uint32_t mb = mb_base + (uint32_t)cur * 8u;
            const uint32_t par = cur ? p1 : p0;
            uint32_t done;
            asm volatile("{\n\t.reg .pred p;\n\t"
                         "mbarrier.try_wait.parity.acquire.cta.shared::cta.b64 p, [%1], %2;\n\t"
                         "selp.b32 %0, 1, 0, p;\n\t}"
                         : "=r"(done) : "r"(mb), "r"(par) : "memory");
            if (!done) {
                asm volatile("{\n\t.reg .pred P1;\n\t"
                             "WL_%=:\n\t"
                             "mbarrier.try_wait.parity.acquire.cta.shared::cta.b64 P1, [%0], %1, 0x989680;\n\t"
                             "@P1 bra.uni WD_%=;\n\t"
                             "bra.uni WL_%=;\n\t"
                             "WD_%=:\n\t}"
                             :: "r"(mb), "r"(par) : "memory");
            }
            if (tid == 0) {   // re-arm for use at t+2 (peers can't fill before our stores)
                asm volatile("mbarrier.arrive.expect_tx.shared.b64 _, [%0], %1;"
                             :: "r"(mb), "r"(4096u) : "memory");
            }
            if (cur) p1 ^= 1; else p0 ^= 1;
        }

        const uint32_t bst = sbase + (uint32_t)cur * SC_STAGE;

        // ---- 2-pass MMA, 4 independent accumulator chains
        float d[2][2][4];
        #pragma unroll
        for (int pl = 0; pl < 2; pl++)
            #pragma unroll
            for (int par2 = 0; par2 < 2; par2++)
                #pragma unroll
                for (int i = 0; i < 4; i++) d[pl][par2][i] = 0.0f;

        #pragma unroll
        for (int ks = 0; ks < 16; ks++) {
            uint32_t b0, b1;
            ldsm_x2t(b0, b1, bst + (uint32_t)ks * 256u + b_lane);
            mma_f16(d[0][ks & 1], a_hi[ks], b0, b1);
            mma_f16(d[1][ks & 1], a_lo[ks], b0, b1);
        }

        // z (own kind) = hi-pass + lo-pass/2048 + xz
        float zo[2][2];
        #pragma unroll
        for (int rr = 0; rr < 2; rr++)
            #pragma unroll
            for (int col = 0; col < 2; col++) {
                int i = rr * 2 + col;
                zo[rr][col] = (d[0][0][i] + d[0][1][i]) +
                              (d[1][0][i] + d[1][1][i]) * (1.0f / 2048.0f) +
                              pf[rr][col];
            }

        // pair f/g via quad exchange (q ^ 1)
        float zx[2][2];
        #pragma unroll
        for (int rr = 0; rr < 2; rr++)
            #pragma unroll
            for (int col = 0; col < 2; col++)
                zx[rr][col] = __shfl_xor_sync(0xffffffffu, zo[rr][col], 4);

        const int nxt = cur ^ 1;
        #pragma unroll
        for (int rr = 0; rr < 2; rr++) {
            __half v01[2];
            #pragma unroll
            for (int col = 0; col < 2; col++) {
                float zf = e ? zx[rr][col] : zo[rr][col];
                float zg = e ? zo[rr][col] : zx[rr][col];
                float f = fast_sigmoid(zf);
                float g = 2.0f * fast_sigmoid(2.0f * zg) - 1.0f;   // tanh
                float c = f * cst[rr][col] + (1.0f - f) * g;
                cst[rr][col] = c;
                v01[col] = __float2half_rn(c);
            }
            if (e == 0) {   // single h plane: even quads store, carrying complete_tx
                uint32_t pk = hpack(v01[0], v01[1]);
                uint32_t off = (uint32_t)nxt * SC_STAGE +
                               (uint32_t)((cell0 + rr * 4) * 16 + n0 * 2);
                #pragma unroll
                for (int p = 0; p < NN; p++) {
                    asm volatile(
                        "st.async.shared::cluster.mbarrier::complete_tx::bytes.b32 [%0], %1, [%2];"
                        :: "r"(peerB[p] + off), "r"(pk), "r"(peerMB[p] + (uint32_t)nxt * 8u)
                        : "memory");
                }
            }
        }

        // ---- prefetch next step's xz
        if (t + 1 < TT) xzp += (size_t)BB * GG;
        pf[0][0] = __ldcs(xzp);      pf[0][1] = __ldcs(xzp + GG);
        pf[1][0] = __ldcs(xzp + 4);  pf[1][1] = __ldcs(xzp + GG + 4);
    }

    // ---- final h (even quads hold canonical values)
    if (e == 0) {
        #pragma unroll
        for (int rr = 0; rr < 2; rr++)
            #pragma unroll
            for (int col = 0; col < 2; col++)
                g_h[((int)tile * 8 + n0 + col) * CC + cell0 + rr * 4] = cst[rr][col];
    }

    // no CTA may exit while peers' st.async targeting its SMEM is in flight
    asm volatile("barrier.cluster.arrive.aligned;" ::: "memory");
    asm volatile("barrier.cluster.wait.aligned;"   ::: "memory");
}

// ============================================================================
// Phase 3: out = h_final @ dense_w + dense_b   (256x256 @ 256x10)
// ============================================================================
__global__ void __launch_bounds__(32) dense_kernel(const float* __restrict__ dw,
                                                   const float* __restrict__ db,
                                                   float* __restrict__ out) {
    int b = blockIdx.x;
    int o = threadIdx.x;
    if (o < OO) {
        float acc = 0.0f;
        #pragma unroll 8
        for (int c = 0; c < CC; c++) {
            acc += g_h[b * CC + c] * dw[c * OO + o];
        }
        out[b * OO + o] = acc + db[o];
    }
}

// ============================================================================
extern "C" void kernel_launch(void* const* d_in, const int* in_sizes, int n_in,
                              void* d_out, int out_size) {
    const float* x  = (const float*)d_in[0];
    const float* wk = (const float*)d_in[1];
    const float* rk = (const float*)d_in[2];
    const float* rb = (const float*)d_in[3];
    const float* dw = (const float*)d_in[4];
    const float* db = (const float*)d_in[5];
    float* out = (float*)d_out;

    // Phase 1: input projection GEMM on tensor cores
    cudaFuncSetAttribute(xz_gemm_tc, cudaFuncAttributeMaxDynamicSharedMemorySize, XG_SMEM);
    xz_gemm_tc<<<dim3(GG / 128, (BB * TT) / 128), XG_THREADS, XG_SMEM>>>(x, wk, rb);

    // Phase 2: fp16 2-pass mma.sync recurrence with st.async mbarrier sync
    janet_scan_mma<<<32 * NN, SC_THREADS>>>(rk);

    // Phase 3: final dense
    dense_kernel<<<BB, 32>>>(dw, db, out);
}

// round 15
// speedup vs baseline: 8.3624x; 1.0456x over previous
#include <cuda_runtime.h>
#include <cuda_bf16.h>
#include <cuda_fp16.h>
#include <cstdint>
#include <cstddef>

// Problem dims
#define BB 256
#define TT 1024
#define II 128
#define CC 256
#define GG 512   // 2C
#define OO 10

// Scratch (static device globals -- allocation-free kernel_launch)
__device__ float g_xz[(size_t)TT * BB * GG];   // [t][b][g]  (512 MB)
__device__ float g_h[BB * CC];                 // final hidden state

__device__ __forceinline__ float fast_sigmoid(float x) {
    return __fdividef(1.0f, 1.0f + __expf(-x));
}

// ---- shared mma.sync helpers (sm_80-class PTX; valid on compute_103) ----
__device__ __forceinline__ void ldsm_x4(uint32_t (&r)[4], uint32_t addr) {
    asm volatile("ldmatrix.sync.aligned.m8n8.x4.shared.b16 {%0,%1,%2,%3}, [%4];"
                 : "=r"(r[0]), "=r"(r[1]), "=r"(r[2]), "=r"(r[3]) : "r"(addr));
}
__device__ __forceinline__ void ldsm_x2t(uint32_t& r0, uint32_t& r1, uint32_t addr) {
    asm volatile("ldmatrix.sync.aligned.m8n8.x2.trans.shared.b16 {%0,%1}, [%2];"
                 : "=r"(r0), "=r"(r1) : "r"(addr));
}
__device__ __forceinline__ void mma_f16(float (&d)[4], const uint32_t (&a)[4],
                                        uint32_t b0, uint32_t b1) {
    asm volatile("mma.sync.aligned.m16n8k16.row.col.f32.f16.f16.f32 "
                 "{%0,%1,%2,%3}, {%4,%5,%6,%7}, {%8,%9}, {%0,%1,%2,%3};"
                 : "+f"(d[0]), "+f"(d[1]), "+f"(d[2]), "+f"(d[3])
                 : "r"(a[0]), "r"(a[1]), "r"(a[2]), "r"(a[3]), "r"(b0), "r"(b1));
}
__device__ __forceinline__ uint32_t hpack(__half a, __half b) {
    return (uint32_t)__half_as_ushort(a) | ((uint32_t)__half_as_ushort(b) << 16);
}
// exact fp16 split, UNSCALED lo (residual <= 2^-11*|v| fits fp16 normals/denormals;
// both passes can then share one fp32 accumulator)
__device__ __forceinline__ void hsplit(float v, __half& h, __half& l) {
    h = __float2half_rn(v);
    l = __float2half_rn(v - __half2float(h));
}

// ============================================================================
// Phase 1: xz = x @ kernel + bias on tensor cores, 2-PASS fp16.
// A = x as fp16 hi + unscaled fp16 lo planes (exact split); B = w single fp16
// plane (2^-11 rel error, empirically attenuated ~10x through the gates).
// CTA tile 128x128, K chunks of 64; per ks: 4 A-ldsm + 8 B-ldsm + 32 HMMA.
// ============================================================================
#define XG_THREADS 256
#define XG_AXH 0                        // x hi: 128 rows x 144 B
#define XG_AXL 18432                    // x lo: 128 rows x 144 B
#define XG_BW  36864                    // w:     64 rows x 272 B
#define XG_SMEM 54272

__global__ void __launch_bounds__(XG_THREADS, 2)
xz_gemm_tc(const float* __restrict__ x, const float* __restrict__ wk,
           const float* __restrict__ bias) {
    extern __shared__ __align__(1024) unsigned char smem[];
    const uint32_t sbase = (uint32_t)__cvta_generic_to_shared(smem);

    const int tid  = threadIdx.x;
    const int w    = tid >> 5;
    const int lane = tid & 31;
    const int warp_m = w >> 1;          // 0..3 -> m rows [32*warp_m, +32)
    const int warp_n = w & 1;           // 0..1 -> n cols [64*warp_n, +64)
    const int m0 = blockIdx.y * 128;
    const int n0 = blockIdx.x * 128;

    const int li = lane & 7, lj = lane >> 3;
    const uint32_t aAddrH = sbase + XG_AXH +
        (uint32_t)((warp_m * 32 + li + (lj & 1) * 8) * 144 + ((lj >> 1) * 8) * 2);
    const uint32_t aAddrL = aAddrH + (XG_AXL - XG_AXH);
    const uint32_t bAddr = sbase + XG_BW +
        (uint32_t)((lane & 15) * 272 + (warp_n * 64) * 2);

    float d[2][8][4];
    #pragma unroll
    for (int mt = 0; mt < 2; mt++)
        #pragma unroll
        for (int nt = 0; nt < 8; nt++)
            #pragma unroll
            for (int i = 0; i < 4; i++) d[mt][nt][i] = 0.0f;

    #pragma unroll
    for (int kc = 0; kc < 2; kc++) {
        // ---- load + split x tile [128 m][64 k] into fp16 hi / lo planes
        #pragma unroll
        for (int i = 0; i < 8; i++) {
            int idx = tid + i * 256;
            int r = idx >> 4, c4 = (idx & 15) * 4;
            float4 v = *(const float4*)(x + (size_t)(m0 + r) * II + kc * 64 + c4);
            __half h0, l0, h1, l1, h2, l2, h3, l3;
            hsplit(v.x, h0, l0); hsplit(v.y, h1, l1);
            hsplit(v.z, h2, l2); hsplit(v.w, h3, l3);
            unsigned char* ph = smem + XG_AXH + r * 144 + c4 * 2;
            unsigned char* pl = smem + XG_AXL + r * 144 + c4 * 2;
            *(__half2*)(ph)     = __halves2half2(h0, h1);
            *(__half2*)(ph + 4) = __halves2half2(h2, h3);
            *(__half2*)(pl)     = __halves2half2(l0, l1);
            *(__half2*)(pl + 4) = __halves2half2(l2, l3);
        }
        // ---- load w tile [64 k][128 n] as single fp16 plane
        #pragma unroll
        for (int i = 0; i < 8; i++) {
            int idx = tid + i * 256;
            int kk = idx >> 5, c4 = (idx & 31) * 4;
            float4 v = *(const float4*)(wk + (size_t)(kc * 64 + kk) * GG + n0 + c4);
            unsigned char* pw = smem + XG_BW + kk * 272 + c4 * 2;
            *(__half2*)(pw)     = __halves2half2(__float2half_rn(v.x), __float2half_rn(v.y));
            *(__half2*)(pw + 4) = __halves2half2(__float2half_rn(v.z), __float2half_rn(v.w));
        }
        __syncthreads();

        #pragma unroll
        for (int ks = 0; ks < 4; ks++) {
            uint32_t ah[2][4], al[2][4];
            #pragma unroll
            for (int mt = 0; mt < 2; mt++) {
                ldsm_x4(ah[mt], aAddrH + (uint32_t)(mt * 2304 + ks * 32));
                ldsm_x4(al[mt], aAddrL + (uint32_t)(mt * 2304 + ks * 32));
            }
            #pragma unroll
            for (int nt = 0; nt < 8; nt++) {
                uint32_t b0, b1;
                ldsm_x2t(b0, b1, bAddr + (uint32_t)(ks * 4352 + nt * 16));
                #pragma unroll
                for (int mt = 0; mt < 2; mt++) {
                    mma_f16(d[mt][nt], ah[mt], b0, b1);   // x_hi * w
                    mma_f16(d[mt][nt], al[mt], b0, b1);   // x_lo * w (same acc, unscaled)
                }
            }
        }
        __syncthreads();
    }

    const int q = lane >> 2, tig = lane & 3;
    #pragma unroll
    for (int nt = 0; nt < 8; nt++) {
        const int col = n0 + warp_n * 64 + nt * 8 + 2 * tig;
        float2 bz = *(const float2*)&bias[col];
        #pragma unroll
        for (int mt = 0; mt < 2; mt++) {
            int mrow = m0 + warp_m * 32 + mt * 16 + q;
            #pragma unroll
            for (int half = 0; half < 2; half++) {
                int m = mrow + half * 8;
                int b = m >> 10, t = m & (TT - 1);
                float2 v;
                v.x = d[mt][nt][2 * half + 0] + bz.x;
                v.y = d[mt][nt][2 * half + 1] + bz.y;
                *(float2*)&g_xz[((size_t)t * BB + b) * GG + col] = v;
            }
        }
    }
}

// ============================================================================
// Phase 2: recurrence, SINGLE-PASS fp16 (W as one fp16 plane in registers;
// h single fp16 plane), st.async + mbarrier complete_tx sync (proven R14).
// Per step per warp: 16 ldsm.x2.trans + 16 HMMA in 4 independent chains.
// ============================================================================
#define NN 4
#define SC_THREADS 256
#define SC_STAGE 4096                 // 256 k-rows x 8 n x fp16

__global__ void __launch_bounds__(SC_THREADS, 1) __cluster_dims__(NN, 1, 1)
janet_scan_mma(const float* __restrict__ rk /* [C][2C] */) {
    __shared__ __align__(1024) unsigned char smem[2 * SC_STAGE + 16];
    const uint32_t sbase = (uint32_t)__cvta_generic_to_shared(smem);
    const uint32_t mb_base = sbase + 2 * SC_STAGE;      // mb[0], mb[1] (8B each)

    const int tid  = threadIdx.x;
    const int w    = tid >> 5;
    const int lane = tid & 31;
    const int q    = lane >> 2;
    const int cq   = lane & 3;
    const int e    = q & 1;

    const unsigned rank = blockIdx.x & (NN - 1);
    const unsigned tile = blockIdx.x >> 2;

    // ---- zero both h stages (h0 = 0)
    for (int i = tid; i < 2 * SC_STAGE / 4; i += SC_THREADS)
        *(uint32_t*)(smem + 4 * i) = 0u;

    // ---- W fragments into registers, single fp16 plane
    uint32_t a_hi[16][4];
    #pragma unroll
    for (int ks = 0; ks < 16; ks++) {
        #pragma unroll
        for (int r = 0; r < 4; r++) {
            int m  = w * 16 + q + (r & 1) * 8;
            int k0 = ks * 16 + 2 * cq + (r >> 1) * 8;
            int col = (m & 1) ? (CC + 64 * (int)rank + (m >> 1))
                              : (64 * (int)rank + (m >> 1));
            float v0 = __ldg(rk + (size_t)k0 * GG + col);
            float v1 = __ldg(rk + (size_t)(k0 + 1) * GG + col);
            a_hi[ks][r] = hpack(__float2half_rn(v0), __float2half_rn(v1));
        }
    }

    // ---- mbarrier init + pre-arm both stages (count 1; expect 4096 B)
    if (tid == 0) {
        asm volatile("mbarrier.init.shared.b64 [%0], 1;" :: "r"(mb_base) : "memory");
        asm volatile("mbarrier.init.shared.b64 [%0], 1;" :: "r"(mb_base + 8) : "memory");
        asm volatile("mbarrier.arrive.expect_tx.shared.b64 _, [%0], %1;"
                     :: "r"(mb_base), "r"(4096u) : "memory");
        asm volatile("mbarrier.arrive.expect_tx.shared.b64 _, [%0], %1;"
                     :: "r"(mb_base + 8), "r"(4096u) : "memory");
    }
    __syncthreads();
    asm volatile("barrier.cluster.arrive.aligned;" ::: "memory");
    asm volatile("barrier.cluster.wait.aligned;"   ::: "memory");

    // ---- peer addresses (B stages + mbarriers)
    uint32_t peerB[NN], peerMB[NN];
    #pragma unroll
    for (int p = 0; p < NN; p++) {
        asm volatile("mapa.shared::cluster.u32 %0, %1, %2;"
                     : "=r"(peerB[p]) : "r"(sbase), "r"(p));
        asm volatile("mapa.shared::cluster.u32 %0, %1, %2;"
                     : "=r"(peerMB[p]) : "r"(mb_base), "r"(p));
    }

    const uint32_t b_lane = (uint32_t)((lane & 15) * 16);
    const int n0    = 2 * cq;
    const int cell0 = 64 * (int)rank + w * 8 + (q >> 1);

    const float* xzp = g_xz + (e ? CC : 0) + (size_t)(tile * 8 + n0) * GG + cell0;
    float pf[2][2];
    pf[0][0] = __ldcs(xzp);      pf[0][1] = __ldcs(xzp + GG);
    pf[1][0] = __ldcs(xzp + 4);  pf[1][1] = __ldcs(xzp + GG + 4);

    float cst[2][2] = {{0.f, 0.f}, {0.f, 0.f}};
    uint32_t p0 = 0, p1 = 0;    // mbarrier phase parities

    for (int t = 0; t < TT; t++) {
        const int cur = t & 1;

        // ---- wait for this stage's h (skip t=0: stage 0 pre-zeroed locally)
        if (t > 0) {
            const uint32_t mb = mb_base + (uint32_t)cur * 8u;
            const uint32_t par = cur ? p1 : p0;
            uint32_t done;
            asm volatile("{\n\t.reg .pred p;\n\t"
                         "mbarrier.try_wait.parity.acquire.cta.shared::cta.b64 p, [%1], %2;\n\t"
                         "selp.b32 %0, 1, 0, p;\n\t}"
                         : "=r"(done) : "r"(mb), "r"(par) : "memory");
            if (!done) {
                asm volatile("{\n\t.reg .pred P1;\n\t"
                             "WL_%=:\n\t"
                             "mbarrier.try_wait.parity.acquire.cta.shared::cta.b64 P1, [%0], %1, 0x989680;\n\t"
                             "@P1 bra.uni WD_%=;\n\t"
                             "bra.uni WL_%=;\n\t"
                             "WD_%=:\n\t}"
                             :: "r"(mb), "r"(par) : "memory");
            }
            if (tid == 0) {   // re-arm for use at t+2
                asm volatile("mbarrier.arrive.expect_tx.shared.b64 _, [%0], %1;"
                             :: "r"(mb), "r"(4096u) : "memory");
            }
            if (cur) p1 ^= 1; else p0 ^= 1;
        }

        const uint32_t bst = sbase + (uint32_t)cur * SC_STAGE;

        // ---- single-pass MMA, 4 independent accumulator chains (depth 4)
        float d[4][4];
        #pragma unroll
        for (int ch = 0; ch < 4; ch++)
            #pragma unroll
            for (int i = 0; i < 4; i++) d[ch][i] = 0.0f;

        #pragma unroll
        for (int ks = 0; ks < 16; ks++) {
            uint32_t b0, b1;
            ldsm_x2t(b0, b1, bst + (uint32_t)ks * 256u + b_lane);
            mma_f16(d[ks & 3], a_hi[ks], b0, b1);
        }

        // z (own kind) = chain sum + xz
        float zo[2][2];
        #pragma unroll
        for (int rr = 0; rr < 2; rr++)
            #pragma unroll
            for (int col = 0; col < 2; col++) {
                int i = rr * 2 + col;
                zo[rr][col] = (d[0][i] + d[1][i]) + (d[2][i] + d[3][i]) + pf[rr][col];
            }

        // pair f/g via quad exchange (q ^ 1)
        float zx[2][2];
        #pragma unroll
        for (int rr = 0; rr < 2; rr++)
            #pragma unroll
            for (int col = 0; col < 2; col++)
                zx[rr][col] = __shfl_xor_sync(0xffffffffu, zo[rr][col], 4);

        const int nxt = cur ^ 1;
        #pragma unroll
        for (int rr = 0; rr < 2; rr++) {
            __half v01[2];
            #pragma unroll
            for (int col = 0; col < 2; col++) {
                float zf = e ? zx[rr][col] : zo[rr][col];
                float zg = e ? zo[rr][col] : zx[rr][col];
                float f = fast_sigmoid(zf);
                float g = 2.0f * fast_sigmoid(2.0f * zg) - 1.0f;   // tanh
                float c = f * cst[rr][col] + (1.0f - f) * g;
                cst[rr][col] = c;
                v01[col] = __float2half_rn(c);
            }
            if (e == 0) {   // even quads store h, carrying complete_tx to peers
                uint32_t pk = hpack(v01[0], v01[1]);
                uint32_t off = (uint32_t)nxt * SC_STAGE +
                               (uint32_t)((cell0 + rr * 4) * 16 + n0 * 2);
                #pragma unroll
                for (int p = 0; p < NN; p++) {
                    asm volatile(
                        "st.async.shared::cluster.mbarrier::complete_tx::bytes.b32 [%0], %1, [%2];"
                        :: "r"(peerB[p] + off), "r"(pk), "r"(peerMB[p] + (uint32_t)nxt * 8u)
                        : "memory");
                }
            }
        }

        // ---- prefetch next step's xz
        if (t + 1 < TT) xzp += (size_t)BB * GG;
        pf[0][0] = __ldcs(xzp);      pf[0][1] = __ldcs(xzp + GG);
        pf[1][0] = __ldcs(xzp + 4);  pf[1][1] = __ldcs(xzp + GG + 4);
    }

    // ---- final h (even quads hold canonical values)
    if (e == 0) {
        #pragma unroll
        for (int rr = 0; rr < 2; rr++)
            #pragma unroll
            for (int col = 0; col < 2; col++)
                g_h[((int)tile * 8 + n0 + col) * CC + cell0 + rr * 4] = cst[rr][col];
    }

    // no CTA may exit while peers' st.async targeting its SMEM is in flight
    asm volatile("barrier.cluster.arrive.aligned;" ::: "memory");
    asm volatile("barrier.cluster.wait.aligned;"   ::: "memory");
}

// ============================================================================
// Phase 3: out = h_final @ dense_w + dense_b   (256x256 @ 256x10)
// ============================================================================
__global__ void __launch_bounds__(32) dense_kernel(const float* __restrict__ dw,
                                                   const float* __restrict__ db,
                                                   float* __restrict__ out) {
    int b = blockIdx.x;
    int o = threadIdx.x;
    if (o < OO) {
        float acc = 0.0f;
        #pragma unroll 8
        for (int c = 0; c < CC; c++) {
            acc += g_h[b * CC + c] * dw[c * OO + o];
        }
        out[b * OO + o] = acc + db[o];
    }
}

// ============================================================================
extern "C" void kernel_launch(void* const* d_in, const int* in_sizes, int n_in,
                              void* d_out, int out_size) {
    const float* x  = (const float*)d_in[0];
    const float* wk = (const float*)d_in[1];
    const float* rk = (const float*)d_in[2];
    const float* rb = (const float*)d_in[3];
    const float* dw = (const float*)d_in[4];
    const float* db = (const float*)d_in[5];
    float* out = (float*)d_out;

    // Phase 1: input projection GEMM on tensor cores (2-pass fp16)
    cudaFuncSetAttribute(xz_gemm_tc, cudaFuncAttributeMaxDynamicSharedMemorySize, XG_SMEM);
    xz_gemm_tc<<<dim3(GG / 128, (BB * TT) / 128), XG_THREADS, XG_SMEM>>>(x, wk, rb);

    // Phase 2: single-pass fp16 mma.sync recurrence with st.async mbarrier sync
    janet_scan_mma<<<32 * NN, SC_THREADS>>>(rk);

    // Phase 3: final dense
    dense_kernel<<<BB, 32>>>(dw, db, out);
}